// round 13
// baseline (speedup 1.0000x reference)
#include <cuda_runtime.h>
#include <cuda_fp16.h>
#include <math.h>
#include <stdint.h>
#include <string.h>

// ================= problem constants =================
#define H     2048
#define E     60
#define II    1408
#define I2    2816
#define ISH   5632
#define ISH2  11264
#define TOPK  4
#define MAXM  1024
#define MAXSLOTS (MAXM*TOPK)

// ================= device scratch =================
static __device__ __half g_hsh [MAXM * ISH];      // silu(gate)*up, shared expert
static __device__ __half g_hr  [MAXSLOTS * II];   // silu(gate)*up, routed
static __device__ float  g_y   [MAXSLOTS * H];
static __device__ __half g_x16 [MAXM * H];
static __device__ float  g_sig [MAXM];
static __device__ int    g_cnt [E];
static __device__ int    g_off [E];
static __device__ int    g_cur [E];
static __device__ int    g_slot_token[MAXSLOTS];
static __device__ float  g_slot_w    [MAXSLOTS];
static __device__ int    g_slot_of   [MAXM * TOPK];
static __device__ int    g_tk_e      [MAXM * TOPK];
static __device__ float  g_tk_w      [MAXM * TOPK];

// ================= small kernels =================
__global__ void zero_counts_kernel() {
    int t = threadIdx.x;
    if (t < E) g_cnt[t] = 0;
}

__global__ void x16_kernel(const float* __restrict__ x, int n) {
    int i = blockIdx.x * blockDim.x + threadIdx.x;
    if (i < n) g_x16[i] = __float2half(x[i]);
}

__global__ void router_kernel(const float* __restrict__ x,
                              const float* __restrict__ gate_w,
                              const float* __restrict__ sgw) {
    __shared__ float xs[H];
    __shared__ float logits[E + 1];
    int m = blockIdx.x;
    const float* xr = x + (size_t)m * H;
    for (int i = threadIdx.x; i < H; i += blockDim.x) xs[i] = xr[i];
    __syncthreads();

    int wid = threadIdx.x >> 5, lane = threadIdx.x & 31;
    for (int e = wid; e <= E; e += 8) {
        const float* wr = (e < E) ? (gate_w + (size_t)e * H) : sgw;
        float acc = 0.f;
        for (int k = lane; k < H; k += 32) acc += xs[k] * wr[k];
        #pragma unroll
        for (int o = 16; o; o >>= 1) acc += __shfl_xor_sync(0xffffffffu, acc, o);
        if (lane == 0) logits[e] = acc;
    }
    __syncthreads();

    if (threadIdx.x == 0) {
        g_sig[m] = 1.f / (1.f + expf(-logits[E]));
        float mx = -1e30f;
        for (int e = 0; e < E; e++) mx = fmaxf(mx, logits[e]);
        float sum = 0.f;
        for (int e = 0; e < E; e++) { float p = expf(logits[e] - mx); logits[e] = p; sum += p; }
        float inv = 1.f / sum;
        for (int k = 0; k < TOPK; k++) {
            int best = 0; float bv = -1.f;
            for (int e = 0; e < E; e++) { float v = logits[e]; if (v > bv) { bv = v; best = e; } }
            logits[best] = -2.f;
            g_tk_e[m * TOPK + k] = best;
            g_tk_w[m * TOPK + k] = bv * inv;
            atomicAdd(&g_cnt[best], 1);
        }
    }
}

__global__ void scan_kernel() {
    if (threadIdx.x == 0) {
        int s = 0;
        for (int e = 0; e < E; e++) { g_off[e] = s; s += g_cnt[e]; g_cur[e] = 0; }
    }
}

__global__ void fill_kernel(int M) {
    int m = blockIdx.x * blockDim.x + threadIdx.x;
    if (m >= M) return;
    for (int k = 0; k < TOPK; k++) {
        int e = g_tk_e[m * TOPK + k];
        int pos = atomicAdd(&g_cur[e], 1);
        int slot = g_off[e] + pos;
        g_slot_token[slot] = m;
        g_slot_w[slot] = g_tk_w[m * TOPK + k];
        g_slot_of[m * TOPK + k] = slot;
    }
}

__device__ __forceinline__ float silu_f(float v) { return v / (1.f + expf(-v)); }

__global__ void combine_kernel(float* __restrict__ out) {
    int m = blockIdx.x;
    int s0 = g_slot_of[m * TOPK + 0];
    int s1 = g_slot_of[m * TOPK + 1];
    int s2 = g_slot_of[m * TOPK + 2];
    int s3 = g_slot_of[m * TOPK + 3];
    for (int hcol = threadIdx.x; hcol < H; hcol += blockDim.x) {
        float v = out[(size_t)m * H + hcol];
        v += g_y[(size_t)s0 * H + hcol];
        v += g_y[(size_t)s1 * H + hcol];
        v += g_y[(size_t)s2 * H + hcol];
        v += g_y[(size_t)s3 * H + hcol];
        out[(size_t)m * H + hcol] = v;
    }
}

// ===== warp-specialized mma.sync GEMM: 96x256 CTA tile =====================
// 512 threads: tid 0..383 = 12 consumer warps (3m x 4n, warp tile 32x64,
// LDSM+MMA only); tid 384..511 = 4 producer warps (A fp16 cp.async, B fp32
// LDG+cvt+STS). 3-stage SMEM ring, named-barrier full/empty handshakes.
// KC=32. FUSE: gate/up 8-col interleave, epilogue silu(g)*u as half2.
// SCALEMODE: 0 none, 1 g_slot_w[slot], 2 rscale[row].
#define KC       32
#define ROWB     80                    // 32 halves (64B) + 16B pad
#define WS_ABYTES (96 * ROWB)          // 7680
#define WS_STAGE  (WS_ABYTES + 256 * ROWB)  // 28160
#define WS_SMEM   (3 * WS_STAGE)       // 84480

__device__ __forceinline__ uint32_t smem_u32(const void* p) {
    uint32_t a;
    asm("{ .reg .u64 t; cvta.to.shared.u64 t, %1; cvt.u32.u64 %0, t; }" : "=r"(a) : "l"(p));
    return a;
}
__device__ __forceinline__ uint32_t h2u(__half2 h) {
    uint32_t u; memcpy(&u, &h, 4); return u;
}

#define CP_ASYNC16(dst, src, srcsize) \
    asm volatile("cp.async.cg.shared.global [%0], [%1], 16, %2;" \
        :: "r"(dst), "l"(src), "r"(srcsize) : "memory")
#define CP_COMMIT() asm volatile("cp.async.commit_group;" ::: "memory")
#define CP_WAIT0()  asm volatile("cp.async.wait_group 0;" ::: "memory")

#define NB_SYNC(id)   asm volatile("bar.sync %0, 512;"   :: "r"(id) : "memory")
#define NB_ARRIVE(id) asm volatile("bar.arrive %0, 512;" :: "r"(id) : "memory")
#define MEMBAR_CTA()  asm volatile("membar.cta;" ::: "memory")

#define LDSM4(r, addr) \
    asm volatile("ldmatrix.sync.aligned.m8n8.x4.shared.b16 {%0,%1,%2,%3}, [%4];" \
        : "=r"((r)[0]), "=r"((r)[1]), "=r"((r)[2]), "=r"((r)[3]) : "r"(addr))

#define MMA_F16(c, a, b0, b1) \
    asm volatile("mma.sync.aligned.m16n8k16.row.col.f32.f16.f16.f32 " \
        "{%0,%1,%2,%3}, {%4,%5,%6,%7}, {%8,%9}, {%0,%1,%2,%3};" \
        : "+f"((c)[0]), "+f"((c)[1]), "+f"((c)[2]), "+f"((c)[3]) \
        : "r"((a)[0]), "r"((a)[1]), "r"((a)[2]), "r"((a)[3]), "r"(b0), "r"(b1))

__device__ __forceinline__ uint4 cvt8(float4 v0, float4 v1) {
    __half2 h0 = __floats2half2_rn(v0.x, v0.y);
    __half2 h1 = __floats2half2_rn(v0.z, v0.w);
    __half2 h2 = __floats2half2_rn(v1.x, v1.y);
    __half2 h3 = __floats2half2_rn(v1.z, v1.w);
    return make_uint4(h2u(h0), h2u(h1), h2u(h2), h2u(h3));
}

// ROUTED: grid.z = expert, rows from g_cnt/g_off; else rows = mrows.
// GATHER: A row via g_slot_token[off+l].
template<int ROUTED, int GATHER, int FUSE, int SCALEMODE>
__global__ void __launch_bounds__(512, 1) ws_gemm(
    const __half* __restrict__ A, int lda,
    const float* __restrict__ Bbase, size_t strideB,
    float* __restrict__ C, int Ntot, int K,
    const float* __restrict__ rscale, int mrows)
{
    extern __shared__ char smem[];
    uint32_t sm0 = smem_u32(smem);

    int cnt = mrows, off = 0;
    const float* Bp = Bbase;
    if (ROUTED) {
        int e = blockIdx.z;
        cnt = g_cnt[e];
        off = g_off[e];
        Bp += (size_t)e * strideB;
    }
    int m0 = blockIdx.y * 96;
    if (m0 >= cnt) return;
    int n0 = blockIdx.x * 256;
    int tid = threadIdx.x;
    int KT = K / KC;

    if (tid >= 384) {
        // ================== PRODUCER (4 warps) ==================
        int tp = tid - 384;   // 0..127

        // A pieces: 96 rows x 4 x 16B = 384 pieces; 3 per thread.
        const char* aS[3]; uint32_t aD[3], aSz[3];
        #pragma unroll
        for (int j = 0; j < 3; j++) {
            int p = tp * 3 + j;
            int row = p >> 2, seg = p & 3;
            int l = m0 + row;
            long ar;
            if (!ROUTED) ar = (l < cnt) ? (long)l : -1;
            else ar = (l < cnt) ? (GATHER ? (long)g_slot_token[off + l] : (long)(off + l)) : -1;
            aS[j] = (const char*)(A + (size_t)(ar < 0 ? 0 : ar) * lda) + seg * 16;
            aD[j] = (uint32_t)(row * ROWB + seg * 16);
            aSz[j] = (ar >= 0) ? 16u : 0u;
        }

        // B rows: 2 per thread (tp, tp+128)
        int rowL0 = n0 + tp, rowL1 = n0 + tp + 128;
        int bR0 = FUSE ? (((rowL0 >> 4) << 3) + (rowL0 & 7) + ((rowL0 & 8) ? (Ntot >> 1) : 0)) : rowL0;
        int bR1 = FUSE ? (((rowL1 >> 4) << 3) + (rowL1 & 7) + ((rowL1 & 8) ? (Ntot >> 1) : 0)) : rowL1;
        const float* b0 = Bp + (size_t)bR0 * K;
        const float* b1 = Bp + (size_t)bR1 * K;
        uint32_t d0 = (uint32_t)(WS_ABYTES + tp * ROWB);
        uint32_t d1 = (uint32_t)(WS_ABYTES + (tp + 128) * ROWB);

        float4 rb0[8], rb1[8];
        #pragma unroll
        for (int q = 0; q < 8; q++) { rb0[q] = *(const float4*)(b0 + 4 * q); rb1[q] = *(const float4*)(b1 + 4 * q); }

        for (int kt = 0; kt < KT; kt++) {
            int s = kt - (kt / 3) * 3;
            if (kt >= 3) NB_SYNC(4 + s);
            uint32_t sb = sm0 + s * WS_STAGE;
            char* sc = smem + s * WS_STAGE;

            // A cp.async for chunk kt
            size_t ao = (size_t)kt * 64;
            #pragma unroll
            for (int j = 0; j < 3; j++) CP_ASYNC16(sb + aD[j], aS[j] + ao, aSz[j]);
            CP_COMMIT();

            // B STS from registers (chunk kt)
            *(uint4*)(sc + d0 +  0) = cvt8(rb0[0], rb0[1]);
            *(uint4*)(sc + d0 + 16) = cvt8(rb0[2], rb0[3]);
            *(uint4*)(sc + d0 + 32) = cvt8(rb0[4], rb0[5]);
            *(uint4*)(sc + d0 + 48) = cvt8(rb0[6], rb0[7]);
            *(uint4*)(sc + d1 +  0) = cvt8(rb1[0], rb1[1]);
            *(uint4*)(sc + d1 + 16) = cvt8(rb1[2], rb1[3]);
            *(uint4*)(sc + d1 + 32) = cvt8(rb1[4], rb1[5]);
            *(uint4*)(sc + d1 + 48) = cvt8(rb1[6], rb1[7]);

            // prefetch B(kt+1)
            if (kt + 1 < KT) {
                const float* p0 = b0 + (kt + 1) * KC;
                const float* p1 = b1 + (kt + 1) * KC;
                #pragma unroll
                for (int q = 0; q < 8; q++) { rb0[q] = *(const float4*)(p0 + 4 * q); rb1[q] = *(const float4*)(p1 + 4 * q); }
            }

            CP_WAIT0();               // A(kt) resident
            MEMBAR_CTA();             // make STS + cp.async writes visible
            NB_ARRIVE(1 + s);         // signal FULL(s)
        }
    } else {
        // ================== CONSUMER (12 warps) ==================
        int lane = tid & 31, cw = tid >> 5;        // cw 0..11
        int wm = cw - (cw / 3) * 3;                // 0..2 (m)
        int wn = cw / 3;                           // 0..3 (n)
        uint32_t lmoff = (uint32_t)((lane & 15) * ROWB + (lane >> 4) * 16);
        uint32_t aB = sm0 + (uint32_t)(wm * 32 * ROWB) + lmoff;
        uint32_t bB = sm0 + WS_ABYTES + (uint32_t)(wn * 64 * ROWB) + lmoff;

        float c[2][8][4];
        #pragma unroll
        for (int i = 0; i < 2; i++)
            #pragma unroll
            for (int j = 0; j < 8; j++)
                #pragma unroll
                for (int q = 0; q < 4; q++) c[i][j][q] = 0.f;

        for (int kt = 0; kt < KT; kt++) {
            int s = kt - (kt / 3) * 3;
            NB_SYNC(1 + s);           // wait FULL(s)
            uint32_t ab = aB + s * WS_STAGE, bb = bB + s * WS_STAGE;
            #pragma unroll
            for (int kk = 0; kk < 2; kk++) {
                uint32_t ah[2][4], bh[4][4];
                #pragma unroll
                for (int mi = 0; mi < 2; mi++)
                    LDSM4(ah[mi], ab + mi * (16 * ROWB) + kk * 32);
                #pragma unroll
                for (int j = 0; j < 4; j++)
                    LDSM4(bh[j], bb + j * (16 * ROWB) + kk * 32);
                #pragma unroll
                for (int mi = 0; mi < 2; mi++)
                    #pragma unroll
                    for (int ns = 0; ns < 8; ns++) {
                        int j = ns >> 1, sel = ns & 1;
                        MMA_F16(c[mi][ns], ah[mi], bh[j][sel], bh[j][sel + 2]);
                    }
            }
            if (kt + 3 < KT) NB_ARRIVE(4 + s);   // free stage for producer
        }

        // ---- epilogue ----
        #pragma unroll
        for (int mi = 0; mi < 2; mi++) {
            int lr0 = m0 + wm * 32 + mi * 16 + (lane >> 2);
            #pragma unroll
            for (int half_ = 0; half_ < 2; half_++) {
                int lr = lr0 + half_ * 8;
                if (lr >= cnt) continue;
                int orow = ROUTED ? (off + lr) : lr;
                if (FUSE) {
                    __half* Ch = (__half*)C;
                    int NH = Ntot >> 1;
                    __half* cp = Ch + (size_t)orow * NH + (n0 >> 1) + wn * 32 + (lane & 3) * 2;
                    #pragma unroll
                    for (int k = 0; k < 4; k++) {
                        float g0 = c[mi][2 * k][half_ * 2 + 0];
                        float u0 = c[mi][2 * k + 1][half_ * 2 + 0];
                        float g1 = c[mi][2 * k][half_ * 2 + 1];
                        float u1 = c[mi][2 * k + 1][half_ * 2 + 1];
                        __half2 v = __floats2half2_rn(silu_f(g0) * u0, silu_f(g1) * u1);
                        *(__half2*)(cp + k * 8) = v;
                    }
                } else {
                    float s = 1.f;
                    if (SCALEMODE == 1) s = g_slot_w[off + lr];
                    if (SCALEMODE == 2) s = rscale[lr];
                    float* cp = C + (size_t)orow * Ntot + n0 + wn * 64 + (lane & 3) * 2;
                    #pragma unroll
                    for (int ns = 0; ns < 8; ns++) {
                        float2 v = make_float2(c[mi][ns][half_ * 2 + 0] * s,
                                               c[mi][ns][half_ * 2 + 1] * s);
                        *(float2*)(cp + ns * 8) = v;
                    }
                }
            }
        }
    }
}

// ================= launch =================
extern "C" void kernel_launch(void* const* d_in, const int* in_sizes, int n_in,
                              void* d_out, int out_size) {
    const float* x      = (const float*)d_in[0];
    const float* gate_w = (const float*)d_in[1];
    const float* sgw    = (const float*)d_in[2];
    const float* w13    = (const float*)d_in[3];
    const float* w2     = (const float*)d_in[4];
    const float* segu   = (const float*)d_in[5];
    const float* sedw   = (const float*)d_in[6];
    float* out = (float*)d_out;

    int M = in_sizes[0] / H;   // 1024
    int mt = (M + 95) / 96;    // 11

    float *y_p, *sig_p;
    __half *hsh_p, *hr_p, *x16_p;
    cudaGetSymbolAddress((void**)&hsh_p, g_hsh);
    cudaGetSymbolAddress((void**)&hr_p,  g_hr);
    cudaGetSymbolAddress((void**)&y_p,   g_y);
    cudaGetSymbolAddress((void**)&sig_p, g_sig);
    cudaGetSymbolAddress((void**)&x16_p, g_x16);

    cudaFuncSetAttribute(ws_gemm<0,0,1,0>, cudaFuncAttributeMaxDynamicSharedMemorySize, WS_SMEM);
    cudaFuncSetAttribute(ws_gemm<0,0,0,2>, cudaFuncAttributeMaxDynamicSharedMemorySize, WS_SMEM);
    cudaFuncSetAttribute(ws_gemm<1,1,1,0>, cudaFuncAttributeMaxDynamicSharedMemorySize, WS_SMEM);
    cudaFuncSetAttribute(ws_gemm<1,0,0,1>, cudaFuncAttributeMaxDynamicSharedMemorySize, WS_SMEM);

    zero_counts_kernel<<<1, 64>>>();
    router_kernel<<<M, 256>>>(x, gate_w, sgw);
    x16_kernel<<<(M * H + 255) / 256, 256>>>(x, M * H);

    // shared expert gate_up + fused silu-mul -> hsh (fp16)
    ws_gemm<0,0,1,0><<<dim3(ISH2 / 256, mt), 512, WS_SMEM>>>(
        x16_p, H, segu, 0, (float*)hsh_p, ISH2, H, nullptr, M);

    scan_kernel<<<1, 32>>>();
    fill_kernel<<<(M + 255) / 256, 256>>>(M);

    // shared expert down proj (scaled by sigmoid gate)
    ws_gemm<0,0,0,2><<<dim3(H / 256, mt), 512, WS_SMEM>>>(
        hsh_p, ISH, sedw, 0, out, H, ISH, sig_p, M);

    // routed gate_up + fused silu-mul -> hr (fp16)
    ws_gemm<1,1,1,0><<<dim3(I2 / 256, mt, E), 512, WS_SMEM>>>(
        x16_p, H, w13, (size_t)I2 * H, (float*)hr_p, I2, H, nullptr, 0);

    // routed down proj (scaled by slot weight)
    ws_gemm<1,0,0,1><<<dim3(H / 256, mt, E), 512, WS_SMEM>>>(
        hr_p, II, w2, (size_t)H * II, y_p, H, II, nullptr, 0);

    // deterministic per-token combine
    combine_kernel<<<M, 256>>>(out);
}

// round 14
// speedup vs baseline: 1.0336x; 1.0336x over previous
#include <cuda_runtime.h>
#include <cuda_fp16.h>
#include <math.h>
#include <stdint.h>
#include <string.h>

// ================= problem constants =================
#define H     2048
#define E     60
#define II    1408
#define I2    2816
#define ISH   5632
#define ISH2  11264
#define TOPK  4
#define MAXM  1024
#define MAXSLOTS (MAXM*TOPK)

// ================= device scratch =================
static __device__ float  g_gu  [MAXM * ISH2];     // dense gate_up out (fp32)
static __device__ float  g_gur [MAXSLOTS * I2];   // routed gate_up out (fp32)
static __device__ __half g_hsh [MAXM * ISH];      // silu(gate)*up, shared (fp16)
static __device__ __half g_hr  [MAXSLOTS * II];   // silu(gate)*up, routed (fp16)
static __device__ float  g_y   [MAXSLOTS * H];
static __device__ __half g_x16 [MAXM * H];
static __device__ float  g_sig [MAXM];
static __device__ int    g_cnt [E];
static __device__ int    g_off [E];
static __device__ int    g_cur [E];
static __device__ int    g_slot_token[MAXSLOTS];
static __device__ float  g_slot_w    [MAXSLOTS];
static __device__ int    g_slot_of   [MAXM * TOPK];
static __device__ int    g_tk_e      [MAXM * TOPK];
static __device__ float  g_tk_w      [MAXM * TOPK];

// ================= small kernels =================
__global__ void zero_counts_kernel() {
    int t = threadIdx.x;
    if (t < E) g_cnt[t] = 0;
}

__global__ void x16_kernel(const float* __restrict__ x, int n) {
    int i = blockIdx.x * blockDim.x + threadIdx.x;
    if (i < n) g_x16[i] = __float2half(x[i]);
}

__global__ void router_kernel(const float* __restrict__ x,
                              const float* __restrict__ gate_w,
                              const float* __restrict__ sgw) {
    __shared__ float xs[H];
    __shared__ float logits[E + 1];
    int m = blockIdx.x;
    const float* xr = x + (size_t)m * H;
    for (int i = threadIdx.x; i < H; i += blockDim.x) xs[i] = xr[i];
    __syncthreads();

    int wid = threadIdx.x >> 5, lane = threadIdx.x & 31;
    for (int e = wid; e <= E; e += 8) {
        const float* wr = (e < E) ? (gate_w + (size_t)e * H) : sgw;
        float acc = 0.f;
        for (int k = lane; k < H; k += 32) acc += xs[k] * wr[k];
        #pragma unroll
        for (int o = 16; o; o >>= 1) acc += __shfl_xor_sync(0xffffffffu, acc, o);
        if (lane == 0) logits[e] = acc;
    }
    __syncthreads();

    if (threadIdx.x == 0) {
        g_sig[m] = 1.f / (1.f + expf(-logits[E]));
        float mx = -1e30f;
        for (int e = 0; e < E; e++) mx = fmaxf(mx, logits[e]);
        float sum = 0.f;
        for (int e = 0; e < E; e++) { float p = expf(logits[e] - mx); logits[e] = p; sum += p; }
        float inv = 1.f / sum;
        for (int k = 0; k < TOPK; k++) {
            int best = 0; float bv = -1.f;
            for (int e = 0; e < E; e++) { float v = logits[e]; if (v > bv) { bv = v; best = e; } }
            logits[best] = -2.f;
            g_tk_e[m * TOPK + k] = best;
            g_tk_w[m * TOPK + k] = bv * inv;
            atomicAdd(&g_cnt[best], 1);
        }
    }
}

__global__ void scan_kernel() {
    if (threadIdx.x == 0) {
        int s = 0;
        for (int e = 0; e < E; e++) { g_off[e] = s; s += g_cnt[e]; g_cur[e] = 0; }
    }
}

__global__ void fill_kernel(int M) {
    int m = blockIdx.x * blockDim.x + threadIdx.x;
    if (m >= M) return;
    for (int k = 0; k < TOPK; k++) {
        int e = g_tk_e[m * TOPK + k];
        int pos = atomicAdd(&g_cur[e], 1);
        int slot = g_off[e] + pos;
        g_slot_token[slot] = m;
        g_slot_w[slot] = g_tk_w[m * TOPK + k];
        g_slot_of[m * TOPK + k] = slot;
    }
}

__device__ __forceinline__ float silu_f(float v) { return v / (1.f + expf(-v)); }

__global__ void silu_mul_kernel(const float* __restrict__ gu, __half* __restrict__ h,
                                int rows, int half_, int full) {
    int total = rows * half_;
    for (int idx = blockIdx.x * blockDim.x + threadIdx.x; idx < total;
         idx += gridDim.x * blockDim.x) {
        int r = idx / half_, i = idx - r * half_;
        float g = gu[(size_t)r * full + i];
        float u = gu[(size_t)r * full + half_ + i];
        h[(size_t)r * half_ + i] = __float2half(silu_f(g) * u);
    }
}

__global__ void combine_kernel(float* __restrict__ out) {
    int m = blockIdx.x;
    int s0 = g_slot_of[m * TOPK + 0];
    int s1 = g_slot_of[m * TOPK + 1];
    int s2 = g_slot_of[m * TOPK + 2];
    int s3 = g_slot_of[m * TOPK + 3];
    for (int hcol = threadIdx.x; hcol < H; hcol += blockDim.x) {
        float v = out[(size_t)m * H + hcol];
        v += g_y[(size_t)s0 * H + hcol];
        v += g_y[(size_t)s1 * H + hcol];
        v += g_y[(size_t)s2 * H + hcol];
        v += g_y[(size_t)s3 * H + hcol];
        out[(size_t)m * H + hcol] = v;
    }
}

// ===== mma.sync GEMM (R6-champion structure + fp16 A via cp.async) =========
// C[M,N] = A[M,K] @ B[N,K]^T.  A fp16 gmem -> cp.async (no regs, no cvt);
// B fp32 -> LDG+cvt+STS.  Tile MTILE x 128 (MTILE = MI*64), KC=64,
// 512 threads (16 warps 4m x 4n, warp tile (MI*16) x 32),
// 2-stage SMEM ring, ONE __syncthreads per chunk.
// MI: 2 dense (128-row tiles), 1 routed (64-row tiles, less padding).
#define KC       64
#define ROWB     144                 // 64 halves (128B) + 16B pad

__device__ __forceinline__ uint32_t smem_u32(const void* p) {
    uint32_t a;
    asm("{ .reg .u64 t; cvta.to.shared.u64 t, %1; cvt.u32.u64 %0, t; }" : "=r"(a) : "l"(p));
    return a;
}
__device__ __forceinline__ uint32_t h2u(__half2 h) {
    uint32_t u; memcpy(&u, &h, 4); return u;
}

#define CP_ASYNC16(dst, src, srcsize) \
    asm volatile("cp.async.cg.shared.global [%0], [%1], 16, %2;" \
        :: "r"(dst), "l"(src), "r"(srcsize) : "memory")
#define CP_COMMIT() asm volatile("cp.async.commit_group;" ::: "memory")
#define CP_WAIT0()  asm volatile("cp.async.wait_group 0;" ::: "memory")

#define LDSM4(r, addr) \
    asm volatile("ldmatrix.sync.aligned.m8n8.x4.shared.b16 {%0,%1,%2,%3}, [%4];" \
        : "=r"((r)[0]), "=r"((r)[1]), "=r"((r)[2]), "=r"((r)[3]) : "r"(addr))

#define MMA_F16(c, a, b0, b1) \
    asm volatile("mma.sync.aligned.m16n8k16.row.col.f32.f16.f16.f32 " \
        "{%0,%1,%2,%3}, {%4,%5,%6,%7}, {%8,%9}, {%0,%1,%2,%3};" \
        : "+f"((c)[0]), "+f"((c)[1]), "+f"((c)[2]), "+f"((c)[3]) \
        : "r"((a)[0]), "r"((a)[1]), "r"((a)[2]), "r"((a)[3]), "r"(b0), "r"(b1))

__device__ __forceinline__ uint4 cvt8(float4 v0, float4 v1) {
    __half2 h0 = __floats2half2_rn(v0.x, v0.y);
    __half2 h1 = __floats2half2_rn(v0.z, v0.w);
    __half2 h2 = __floats2half2_rn(v1.x, v1.y);
    __half2 h3 = __floats2half2_rn(v1.z, v1.w);
    return make_uint4(h2u(h0), h2u(h1), h2u(h2), h2u(h3));
}

// GATHER: A row via g_slot_token[off+l]; ROUTED: grid.z = expert.
// SCALEMODE: 0 none, 1 g_slot_w[slot], 2 rscale[row].
template<int MI, int GATHER, int ROUTED, int SCALEMODE>
__global__ void __launch_bounds__(512, 1) mma_gemm(
    const __half* __restrict__ A, int lda,
    const float* __restrict__ Bbase, size_t strideB,
    float* __restrict__ C, int Ntot, int K,
    const float* __restrict__ rscale)
{
    constexpr int MTILE   = MI * 64;
    constexpr int A_BYTES = MTILE * ROWB;
    constexpr int STAGE   = A_BYTES + 128 * ROWB;

    extern __shared__ char smem[];
    int cnt = 0x3fffffff, off = 0, m0 = blockIdx.y * MTILE;
    const float* Bp = Bbase;
    if (ROUTED) {
        int e = blockIdx.z;
        cnt = g_cnt[e];
        if (m0 >= cnt) return;
        off = g_off[e];
        Bp += (size_t)e * strideB;
    }
    int n0 = blockIdx.x * 128;
    int tid = threadIdx.x;

    // ---- A loader (fp16 cp.async). Chunk-row = 64 halves = 128B = 8x16B. ----
    // MI=2: 1024 pieces, 2/thread (contiguous 32B); MI=1: 512 pieces, 1/thread.
    int rowA, segA;
    if (MI == 2) { rowA = tid >> 2; segA = (tid & 3) * 2; }
    else         { rowA = tid >> 3; segA = tid & 7; }
    long arow;
    if (!ROUTED) arow = m0 + rowA;
    else {
        int l = m0 + rowA;
        arow = (l < cnt) ? (GATHER ? (long)g_slot_token[off + l] : (long)(off + l)) : -1;
    }
    bool av = (arow >= 0);
    const char* aSrc = (const char*)(A + (size_t)(av ? arow : 0) * lda) + segA * 16;
    uint32_t aDst = (uint32_t)(rowA * ROWB + segA * 16);
    uint32_t aSize = av ? 16u : 0u;

    // ---- B loader (fp32): 4 thr/row; thread covers fp32 cols cq..cq+7 and cq+32..cq+39
    int rB = tid >> 2, cqB = (tid & 3) * 8;
    const float* bpf = Bp + (size_t)(n0 + rB) * K + cqB;
    uint32_t bD = (uint32_t)(A_BYTES + rB * ROWB + cqB * 2);

    uint32_t sm0 = smem_u32(smem);

    // ---- ldmatrix bases: 16 warps = 4(m) x 4(n) ----
    int lane = tid & 31, wid = tid >> 5;
    int wm = wid & 3, wn = wid >> 2;
    uint32_t lmoff = (uint32_t)((lane & 15) * ROWB + (lane >> 4) * 16);
    uint32_t aBase = sm0 + (uint32_t)(wm * (MI * 16) * ROWB) + lmoff;
    uint32_t bBase = sm0 + A_BYTES + (uint32_t)(wn * 32 * ROWB) + lmoff;

    float c[MI][4][4];
    #pragma unroll
    for (int i = 0; i < MI; i++)
        #pragma unroll
        for (int j = 0; j < 4; j++)
            #pragma unroll
            for (int q = 0; q < 4; q++) c[i][j][q] = 0.f;

    int KT = K / KC;
    float4 rb[4];

    // ---- prologue: chunk 0 -> stage 0 ----
    CP_ASYNC16(sm0 + aDst, aSrc, aSize);
    if (MI == 2) CP_ASYNC16(sm0 + aDst + 16, aSrc + 16, aSize);
    CP_COMMIT();
    rb[0] = *(const float4*)(bpf + 0);
    rb[1] = *(const float4*)(bpf + 4);
    rb[2] = *(const float4*)(bpf + 32);
    rb[3] = *(const float4*)(bpf + 36);
    *(uint4*)(smem + bD + 0)  = cvt8(rb[0], rb[1]);
    *(uint4*)(smem + bD + 64) = cvt8(rb[2], rb[3]);

    for (int kt = 0; kt < KT; kt++) {
        CP_WAIT0();                       // A(kt) resident
        __syncthreads();                  // B(kt) visible; other stage freed
        bool more = (kt + 1 < KT);
        uint32_t stN = (uint32_t)((kt + 1) & 1) * STAGE;
        uint32_t st  = (uint32_t)(kt & 1) * STAGE;
        uint32_t ab = aBase + st, bb = bBase + st;

        if (more) {
            const char* as = aSrc + (size_t)(kt + 1) * 128;   // 64 halves = 128B
            CP_ASYNC16(sm0 + stN + aDst, as, aSize);
            if (MI == 2) CP_ASYNC16(sm0 + stN + aDst + 16, as + 16, aSize);
            CP_COMMIT();
            const float* bp = bpf + (kt + 1) * KC;
            rb[0] = *(const float4*)(bp + 0);
            rb[1] = *(const float4*)(bp + 4);
            rb[2] = *(const float4*)(bp + 32);
            rb[3] = *(const float4*)(bp + 36);
        }

        // ---- MMA kk=0,1 ----
        #pragma unroll
        for (int kk = 0; kk < 2; kk++) {
            uint32_t ah[MI][4], bh[2][4];
            #pragma unroll
            for (int mi = 0; mi < MI; mi++)
                LDSM4(ah[mi], ab + mi * (16 * ROWB) + kk * 32);
            #pragma unroll
            for (int j = 0; j < 2; j++)
                LDSM4(bh[j], bb + j * (16 * ROWB) + kk * 32);
            #pragma unroll
            for (int mi = 0; mi < MI; mi++)
                #pragma unroll
                for (int ns = 0; ns < 4; ns++) {
                    int j = ns >> 1, sel = ns & 1;
                    MMA_F16(c[mi][ns], ah[mi], bh[j][sel], bh[j][sel + 2]);
                }
        }

        // ---- B wave 0 store ----
        if (more)
            *(uint4*)(smem + stN + bD + 0) = cvt8(rb[0], rb[1]);

        // ---- MMA kk=2,3 ----
        #pragma unroll
        for (int kk = 2; kk < 4; kk++) {
            uint32_t ah[MI][4], bh[2][4];
            #pragma unroll
            for (int mi = 0; mi < MI; mi++)
                LDSM4(ah[mi], ab + mi * (16 * ROWB) + kk * 32);
            #pragma unroll
            for (int j = 0; j < 2; j++)
                LDSM4(bh[j], bb + j * (16 * ROWB) + kk * 32);
            #pragma unroll
            for (int mi = 0; mi < MI; mi++)
                #pragma unroll
                for (int ns = 0; ns < 4; ns++) {
                    int j = ns >> 1, sel = ns & 1;
                    MMA_F16(c[mi][ns], ah[mi], bh[j][sel], bh[j][sel + 2]);
                }
        }

        // ---- B wave 1 store ----
        if (more)
            *(uint4*)(smem + stN + bD + 64) = cvt8(rb[2], rb[3]);
    }

    // ---- epilogue ----
    #pragma unroll
    for (int mi = 0; mi < MI; mi++) {
        int lr0 = m0 + wm * (MI * 16) + mi * 16 + (lane >> 2);
        #pragma unroll
        for (int half_ = 0; half_ < 2; half_++) {
            int lr = lr0 + half_ * 8;
            bool valid = !ROUTED || (lr < cnt);
            if (!valid) continue;
            int orow = ROUTED ? (off + lr) : lr;
            float s = 1.f;
            if (SCALEMODE == 1) s = g_slot_w[off + lr];
            if (SCALEMODE == 2) s = rscale[lr];
            float* cp = C + (size_t)orow * Ntot + n0 + wn * 32 + (lane & 3) * 2;
            #pragma unroll
            for (int ns = 0; ns < 4; ns++) {
                float2 v = make_float2(c[mi][ns][half_ * 2 + 0] * s,
                                       c[mi][ns][half_ * 2 + 1] * s);
                *(float2*)(cp + ns * 8) = v;
            }
        }
    }
}

// ================= launch =================
extern "C" void kernel_launch(void* const* d_in, const int* in_sizes, int n_in,
                              void* d_out, int out_size) {
    const float* x      = (const float*)d_in[0];
    const float* gate_w = (const float*)d_in[1];
    const float* sgw    = (const float*)d_in[2];
    const float* w13    = (const float*)d_in[3];
    const float* w2     = (const float*)d_in[4];
    const float* segu   = (const float*)d_in[5];
    const float* sedw   = (const float*)d_in[6];
    float* out = (float*)d_out;

    int M = in_sizes[0] / H;   // 1024

    float *gu_p, *gur_p, *y_p, *sig_p;
    __half *hsh_p, *hr_p, *x16_p;
    cudaGetSymbolAddress((void**)&gu_p,  g_gu);
    cudaGetSymbolAddress((void**)&gur_p, g_gur);
    cudaGetSymbolAddress((void**)&hsh_p, g_hsh);
    cudaGetSymbolAddress((void**)&hr_p,  g_hr);
    cudaGetSymbolAddress((void**)&y_p,   g_y);
    cudaGetSymbolAddress((void**)&sig_p, g_sig);
    cudaGetSymbolAddress((void**)&x16_p, g_x16);

    const int SMEM_D = 2 * ((128 + 128) * ROWB);   // 73728
    const int SMEM_R = 2 * ((64 + 128) * ROWB);    // 55296

    cudaFuncSetAttribute(mma_gemm<2,0,0,0>, cudaFuncAttributeMaxDynamicSharedMemorySize, SMEM_D);
    cudaFuncSetAttribute(mma_gemm<2,0,0,2>, cudaFuncAttributeMaxDynamicSharedMemorySize, SMEM_D);
    cudaFuncSetAttribute(mma_gemm<1,1,1,0>, cudaFuncAttributeMaxDynamicSharedMemorySize, SMEM_R);
    cudaFuncSetAttribute(mma_gemm<1,0,1,1>, cudaFuncAttributeMaxDynamicSharedMemorySize, SMEM_R);

    // routing pipeline
    zero_counts_kernel<<<1, 64>>>();
    router_kernel<<<M, 256>>>(x, gate_w, sgw);
    scan_kernel<<<1, 32>>>();
    fill_kernel<<<(M + 255) / 256, 256>>>(M);
    x16_kernel<<<(M * H + 255) / 256, 256>>>(x, M * H);

    // shared expert (dense, 128x128 tiles)
    mma_gemm<2,0,0,0><<<dim3(ISH2 / 128, M / 128), 512, SMEM_D>>>(
        x16_p, H, segu, 0, gu_p, ISH2, H, nullptr);
    silu_mul_kernel<<<1024, 256>>>(gu_p, hsh_p, M, ISH, ISH2);
    mma_gemm<2,0,0,2><<<dim3(H / 128, M / 128), 512, SMEM_D>>>(
        hsh_p, ISH, sedw, 0, out, H, ISH, sig_p);

    // routed experts (64-row m-tiles, R6 champion granularity)
    int mtiles = M / 64;   // worst case: all tokens on one expert
    mma_gemm<1,1,1,0><<<dim3(I2 / 128, mtiles, E), 512, SMEM_R>>>(
        x16_p, H, w13, (size_t)I2 * H, gur_p, I2, H, nullptr);
    silu_mul_kernel<<<1024, 256>>>(gur_p, hr_p, M * TOPK, II, I2);
    mma_gemm<1,0,1,1><<<dim3(H / 128, mtiles, E), 512, SMEM_R>>>(
        hr_p, II, w2, (size_t)H * II, y_p, H, II, nullptr);

    // deterministic per-token combine
    combine_kernel<<<M, 256>>>(out);
}

// round 15
// speedup vs baseline: 1.5466x; 1.4963x over previous
#include <cuda_runtime.h>
#include <cuda_fp16.h>
#include <math.h>
#include <stdint.h>
#include <string.h>

// ================= problem constants =================
#define H     2048
#define E     60
#define II    1408
#define I2    2816
#define ISH   5632
#define ISH2  11264
#define TOPK  4
#define MAXM  1024
#define MAXSLOTS (MAXM*TOPK)

// ================= device scratch =================
static __device__ float  g_gu  [MAXM * ISH2];
static __device__ float  g_hsh [MAXM * ISH];
static __device__ float  g_gur [MAXSLOTS * I2];
static __device__ float  g_hr  [MAXSLOTS * II];
static __device__ float  g_y   [MAXSLOTS * H];
static __device__ __half g_x16 [MAXM * H];
static __device__ float  g_sig [MAXM];
static __device__ int    g_cnt [E];
static __device__ int    g_off [E];
static __device__ int    g_cur [E];
static __device__ int    g_slot_token[MAXSLOTS];
static __device__ float  g_slot_w    [MAXSLOTS];
static __device__ int    g_slot_of   [MAXM * TOPK];
static __device__ int    g_tk_e      [MAXM * TOPK];
static __device__ float  g_tk_w      [MAXM * TOPK];

// ================= small kernels =================
__global__ void zero_counts_kernel() {
    int t = threadIdx.x;
    if (t < E) g_cnt[t] = 0;
}

__global__ void x16_kernel(const float* __restrict__ x, int n) {
    int i = blockIdx.x * blockDim.x + threadIdx.x;
    if (i < n) g_x16[i] = __float2half(x[i]);
}

__global__ void router_kernel(const float* __restrict__ x,
                              const float* __restrict__ gate_w,
                              const float* __restrict__ sgw) {
    __shared__ float xs[H];
    __shared__ float logits[E + 1];
    int m = blockIdx.x;
    const float* xr = x + (size_t)m * H;
    for (int i = threadIdx.x; i < H; i += blockDim.x) xs[i] = xr[i];
    __syncthreads();

    int wid = threadIdx.x >> 5, lane = threadIdx.x & 31;
    for (int e = wid; e <= E; e += 8) {
        const float* wr = (e < E) ? (gate_w + (size_t)e * H) : sgw;
        float acc = 0.f;
        for (int k = lane; k < H; k += 32) acc += xs[k] * wr[k];
        #pragma unroll
        for (int o = 16; o; o >>= 1) acc += __shfl_xor_sync(0xffffffffu, acc, o);
        if (lane == 0) logits[e] = acc;
    }
    __syncthreads();

    if (threadIdx.x == 0) {
        g_sig[m] = 1.f / (1.f + expf(-logits[E]));
        float mx = -1e30f;
        for (int e = 0; e < E; e++) mx = fmaxf(mx, logits[e]);
        float sum = 0.f;
        for (int e = 0; e < E; e++) { float p = expf(logits[e] - mx); logits[e] = p; sum += p; }
        float inv = 1.f / sum;
        for (int k = 0; k < TOPK; k++) {
            int best = 0; float bv = -1.f;
            for (int e = 0; e < E; e++) { float v = logits[e]; if (v > bv) { bv = v; best = e; } }
            logits[best] = -2.f;
            g_tk_e[m * TOPK + k] = best;
            g_tk_w[m * TOPK + k] = bv * inv;
            atomicAdd(&g_cnt[best], 1);
        }
    }
}

__global__ void scan_kernel() {
    if (threadIdx.x == 0) {
        int s = 0;
        for (int e = 0; e < E; e++) { g_off[e] = s; s += g_cnt[e]; g_cur[e] = 0; }
    }
}

__global__ void fill_kernel(int M) {
    int m = blockIdx.x * blockDim.x + threadIdx.x;
    if (m >= M) return;
    for (int k = 0; k < TOPK; k++) {
        int e = g_tk_e[m * TOPK + k];
        int pos = atomicAdd(&g_cur[e], 1);
        int slot = g_off[e] + pos;
        g_slot_token[slot] = m;
        g_slot_w[slot] = g_tk_w[m * TOPK + k];
        g_slot_of[m * TOPK + k] = slot;
    }
}

__device__ __forceinline__ float silu_f(float v) { return v / (1.f + expf(-v)); }

__global__ void silu_mul_kernel(const float* __restrict__ gu, float* __restrict__ h,
                                int rows, int half_, int full) {
    int total = rows * half_;
    for (int idx = blockIdx.x * blockDim.x + threadIdx.x; idx < total;
         idx += gridDim.x * blockDim.x) {
        int r = idx / half_, i = idx - r * half_;
        float g = gu[(size_t)r * full + i];
        float u = gu[(size_t)r * full + half_ + i];
        h[(size_t)r * half_ + i] = silu_f(g) * u;
    }
}

__global__ void combine_kernel(float* __restrict__ out) {
    int m = blockIdx.x;
    int s0 = g_slot_of[m * TOPK + 0];
    int s1 = g_slot_of[m * TOPK + 1];
    int s2 = g_slot_of[m * TOPK + 2];
    int s3 = g_slot_of[m * TOPK + 3];
    for (int hcol = threadIdx.x; hcol < H; hcol += blockDim.x) {
        float v = out[(size_t)m * H + hcol];
        v += g_y[(size_t)s0 * H + hcol];
        v += g_y[(size_t)s1 * H + hcol];
        v += g_y[(size_t)s2 * H + hcol];
        v += g_y[(size_t)s3 * H + hcol];
        out[(size_t)m * H + hcol] = v;
    }
}

// ================= shared GEMM helpers =================
__device__ __forceinline__ uint32_t smem_u32(const void* p) {
    uint32_t a;
    asm("{ .reg .u64 t; cvta.to.shared.u64 t, %1; cvt.u32.u64 %0, t; }" : "=r"(a) : "l"(p));
    return a;
}
__device__ __forceinline__ uint32_t h2u(__half2 h) {
    uint32_t u; memcpy(&u, &h, 4); return u;
}

#define CP_ASYNC16(dst, src, srcsize) \
    asm volatile("cp.async.cg.shared.global [%0], [%1], 16, %2;" \
        :: "r"(dst), "l"(src), "r"(srcsize) : "memory")
#define CP_COMMIT() asm volatile("cp.async.commit_group;" ::: "memory")
#define CP_WAIT0()  asm volatile("cp.async.wait_group 0;" ::: "memory")

#define LDSM4(r, addr) \
    asm volatile("ldmatrix.sync.aligned.m8n8.x4.shared.b16 {%0,%1,%2,%3}, [%4];" \
        : "=r"((r)[0]), "=r"((r)[1]), "=r"((r)[2]), "=r"((r)[3]) : "r"(addr))

#define MMA_F16(c, a, b0, b1) \
    asm volatile("mma.sync.aligned.m16n8k16.row.col.f32.f16.f16.f32 " \
        "{%0,%1,%2,%3}, {%4,%5,%6,%7}, {%8,%9}, {%0,%1,%2,%3};" \
        : "+f"((c)[0]), "+f"((c)[1]), "+f"((c)[2]), "+f"((c)[3]) \
        : "r"((a)[0]), "r"((a)[1]), "r"((a)[2]), "r"((a)[3]), "r"(b0), "r"(b1))

__device__ __forceinline__ uint4 cvt8(float4 v0, float4 v1) {
    __half2 h0 = __floats2half2_rn(v0.x, v0.y);
    __half2 h1 = __floats2half2_rn(v0.z, v0.w);
    __half2 h2 = __floats2half2_rn(v1.x, v1.y);
    __half2 h3 = __floats2half2_rn(v1.z, v1.w);
    return make_uint4(h2u(h0), h2u(h1), h2u(h2), h2u(h3));
}

// ===== CHAMPION engine (R6, byte-identical except loads hoisted above bar) ==
// Tile MTILE x 128 (MTILE = MI*64), KC=64 fp32/chunk, 512 threads (16 warps
// 4m x 4n, warp tile (MI*16) x 32), fp32 A+B reg-staged, 2-stage ring.
#define KC       64
#define ROWB     144                 // 64 halves + 8 pad

template<int MI, int GATHER, int ROUTED, int SCALEMODE>
__global__ void __launch_bounds__(512, 1) mma_gemm(
    const float* __restrict__ A, int lda,
    const float* __restrict__ Bbase, size_t strideB,
    float* __restrict__ C, int Ntot, int K,
    const float* __restrict__ rscale)
{
    constexpr int MTILE   = MI * 64;
    constexpr int A_BYTES = MTILE * ROWB;
    constexpr int STAGE   = (MTILE + 128) * ROWB;

    extern __shared__ char smem[];
    int cnt = 0x3fffffff, off = 0, m0 = blockIdx.y * MTILE;
    const float* Bp = Bbase;
    if (ROUTED) {
        int e = blockIdx.z;
        cnt = g_cnt[e];
        if (m0 >= cnt) return;
        off = g_off[e];
        Bp += (size_t)e * strideB;
    }
    int n0 = blockIdx.x * 128;
    int tid = threadIdx.x;

    // ---- A loader mapping ----
    int rA, cqA;
    if (MI == 2) { rA = tid >> 2; cqA = (tid & 3) << 3; }
    else         { rA = tid >> 3; cqA = (tid & 7) << 3; }
    long arow;
    if (!ROUTED) arow = m0 + rA;
    else {
        int l = m0 + rA;
        arow = (l < cnt) ? (GATHER ? (long)g_slot_token[off + l] : (long)(off + l)) : -1;
    }
    bool av = (arow >= 0);
    const float* apf = A + (size_t)(av ? arow : 0) * lda + cqA;
    uint32_t swA0 = (uint32_t)(rA * ROWB + cqA * 2);
    uint32_t swA1 = swA0 + 64;            // MI==2 only

    // ---- B loader mapping ----
    int rB = tid >> 2, cqB = (tid & 3) << 3;
    const float* bpf = Bp + (size_t)(n0 + rB) * K + cqB;
    uint32_t swB0 = (uint32_t)(A_BYTES + rB * ROWB + cqB * 2);
    uint32_t swB1 = swB0 + 64;

    uint32_t sm0 = smem_u32(smem);

    // ---- ldmatrix bases ----
    int lane = tid & 31, wid = tid >> 5;
    int wm = wid & 3, wn = wid >> 2;
    uint32_t lmoff = (uint32_t)((lane & 15) * ROWB + (lane >> 4) * 16);
    uint32_t aBase = sm0 + (uint32_t)(wm * (MI * 16) * ROWB) + lmoff;
    uint32_t bBase = sm0 + A_BYTES + (uint32_t)(wn * 32 * ROWB) + lmoff;

    float c[MI][4][4];
    #pragma unroll
    for (int i = 0; i < MI; i++)
        #pragma unroll
        for (int j = 0; j < 4; j++)
            #pragma unroll
            for (int q = 0; q < 4; q++) c[i][j][q] = 0.f;

    int KT = K / KC;
    const float4 z4 = make_float4(0.f, 0.f, 0.f, 0.f);
    float4 ra[4], rb[4];

    // prologue: chunk 0 -> regs -> stage 0
    ra[0] = av ? *(const float4*)(apf + 0) : z4;
    ra[1] = av ? *(const float4*)(apf + 4) : z4;
    if (MI == 2) {
        ra[2] = av ? *(const float4*)(apf + 32) : z4;
        ra[3] = av ? *(const float4*)(apf + 36) : z4;
    }
    #pragma unroll
    for (int q = 0; q < 2; q++) {
        rb[2*q+0] = *(const float4*)(bpf + 32*q + 0);
        rb[2*q+1] = *(const float4*)(bpf + 32*q + 4);
    }
    {
        *(uint4*)(smem + swA0) = cvt8(ra[0], ra[1]);
        if (MI == 2) *(uint4*)(smem + swA1) = cvt8(ra[2], ra[3]);
        *(uint4*)(smem + swB0) = cvt8(rb[0], rb[1]);
        *(uint4*)(smem + swB1) = cvt8(rb[2], rb[3]);
    }

    for (int kt = 0; kt < KT; kt++) {
        bool more = (kt + 1 < KT);
        // loads hoisted above the barrier: pure register writes, in flight
        // while this warp waits at the barrier.
        if (more) {
            const float* ap = apf + (kt + 1) * KC;
            const float* bp = bpf + (kt + 1) * KC;
            ra[0] = av ? *(const float4*)(ap + 0) : z4;
            ra[1] = av ? *(const float4*)(ap + 4) : z4;
            if (MI == 2) {
                ra[2] = av ? *(const float4*)(ap + 32) : z4;
                ra[3] = av ? *(const float4*)(ap + 36) : z4;
            }
            #pragma unroll
            for (int q = 0; q < 2; q++) {
                rb[2*q+0] = *(const float4*)(bp + 32*q + 0);
                rb[2*q+1] = *(const float4*)(bp + 32*q + 4);
            }
        }
        __syncthreads();

        // MMAs on current stage
        uint32_t st = (uint32_t)(kt & 1) * STAGE;
        uint32_t ab = aBase + st, bb = bBase + st;
        #pragma unroll
        for (int kk = 0; kk < 4; kk++) {
            uint32_t ah[MI][4], bh[2][4];
            #pragma unroll
            for (int mi = 0; mi < MI; mi++)
                LDSM4(ah[mi], ab + mi * (16 * ROWB) + kk * 32);
            #pragma unroll
            for (int j = 0; j < 2; j++)
                LDSM4(bh[j], bb + j * (16 * ROWB) + kk * 32);
            #pragma unroll
            for (int mi = 0; mi < MI; mi++) {
                #pragma unroll
                for (int ns = 0; ns < 4; ns++) {
                    int j = ns >> 1, sel = ns & 1;
                    MMA_F16(c[mi][ns], ah[mi], bh[j][sel], bh[j][sel + 2]);
                }
            }
        }

        // convert+store chunk kt+1 into the other stage
        if (more) {
            char* sb = smem + ((kt + 1) & 1) * STAGE;
            *(uint4*)(sb + swA0) = cvt8(ra[0], ra[1]);
            if (MI == 2) *(uint4*)(sb + swA1) = cvt8(ra[2], ra[3]);
            *(uint4*)(sb + swB0) = cvt8(rb[0], rb[1]);
            *(uint4*)(sb + swB1) = cvt8(rb[2], rb[3]);
        }
    }

    // ---- epilogue ----
    #pragma unroll
    for (int mi = 0; mi < MI; mi++) {
        int lr0 = m0 + wm * (MI * 16) + mi * 16 + (lane >> 2);
        #pragma unroll
        for (int half_ = 0; half_ < 2; half_++) {
            int lr = lr0 + half_ * 8;
            bool valid = !ROUTED || (lr < cnt);
            if (!valid) continue;
            int orow = ROUTED ? (off + lr) : lr;
            float s = 1.f;
            if (SCALEMODE == 1) s = g_slot_w[off + lr];
            if (SCALEMODE == 2) s = rscale[lr];
            float* cp = C + (size_t)orow * Ntot + n0 + wn * 32 + (lane & 3) * 2;
            #pragma unroll
            for (int ns = 0; ns < 4; ns++) {
                float2 v = make_float2(c[mi][ns][half_ * 2 + 0] * s,
                                       c[mi][ns][half_ * 2 + 1] * s);
                *(float2*)(cp + ns * 8) = v;
            }
        }
    }
}

// ===== R7 dense engine (measured 277us on dense1): 128x256, KC=32 ==========
// A fp16 gmem -> cp.async; B fp32 -> LDG+cvt+STS. 512 thr, 16 warps 4m x 4n,
// warp tile 32x64, 2-stage ring, one barrier per chunk.
#define DROWB   80                   // 32 halves (64B) + 16B pad
#define D_AB    (128 * DROWB)        // 10240
#define D_STG   (D_AB + 256 * DROWB) // 30720
#define D_SMEM  (2 * D_STG)          // 61440

template<int SCALEMODE>
__global__ void __launch_bounds__(512, 1) dense_gemm(
    const __half* __restrict__ A, int lda,
    const float* __restrict__ B,
    float* __restrict__ C, int Ntot, int K,
    const float* __restrict__ rscale)
{
    extern __shared__ char smem[];
    int m0 = blockIdx.y * 128;
    int n0 = blockIdx.x * 256;
    int tid = threadIdx.x;

    int rA = tid >> 2;
    int pA = (tid & 3) << 4;
    const char* aSrc = (const char*)(A + (size_t)(m0 + rA) * lda) + pA;
    uint32_t aDst = (uint32_t)(rA * DROWB + pA);

    int rB = tid >> 1, hB = tid & 1;
    const float* bpf = B + (size_t)(n0 + rB) * K + hB * 16;
    uint32_t bDst = (uint32_t)(D_AB + rB * DROWB + hB * 32);

    uint32_t sm0 = smem_u32(smem);
    int lane = tid & 31, wid = tid >> 5;
    int wm = wid & 3, wn = wid >> 2;
    uint32_t lmoff = (uint32_t)((lane & 15) * DROWB + (lane >> 4) * 16);
    uint32_t aBase = sm0 + (uint32_t)(wm * 32 * DROWB) + lmoff;
    uint32_t bBase = sm0 + D_AB + (uint32_t)(wn * 64 * DROWB) + lmoff;

    float c[2][8][4];
    #pragma unroll
    for (int i = 0; i < 2; i++)
        #pragma unroll
        for (int j = 0; j < 8; j++)
            #pragma unroll
            for (int q = 0; q < 4; q++) c[i][j][q] = 0.f;

    int KT = K / 32;
    float4 rb[4];

    CP_ASYNC16(sm0 + aDst, aSrc, 16);
    CP_COMMIT();
    #pragma unroll
    for (int q = 0; q < 4; q++) rb[q] = *(const float4*)(bpf + 4 * q);
    *(uint4*)(smem + bDst + 0)  = cvt8(rb[0], rb[1]);
    *(uint4*)(smem + bDst + 16) = cvt8(rb[2], rb[3]);

    for (int kt = 0; kt < KT; kt++) {
        CP_WAIT0();
        __syncthreads();
        bool more = (kt + 1 < KT);
        uint32_t stN = (uint32_t)((kt + 1) & 1) * D_STG;
        if (more) {
            CP_ASYNC16(sm0 + stN + aDst, aSrc + (size_t)(kt + 1) * 64, 16);
            CP_COMMIT();
            const float* bp = bpf + (kt + 1) * 32;
            #pragma unroll
            for (int q = 0; q < 4; q++) rb[q] = *(const float4*)(bp + 4 * q);
        }

        uint32_t st = (uint32_t)(kt & 1) * D_STG;
        uint32_t ab = aBase + st, bb = bBase + st;
        #pragma unroll
        for (int kk = 0; kk < 2; kk++) {
            uint32_t ah[2][4], bh[4][4];
            #pragma unroll
            for (int mi = 0; mi < 2; mi++)
                LDSM4(ah[mi], ab + mi * (16 * DROWB) + kk * 32);
            #pragma unroll
            for (int j = 0; j < 4; j++)
                LDSM4(bh[j], bb + j * (16 * DROWB) + kk * 32);
            #pragma unroll
            for (int mi = 0; mi < 2; mi++)
                #pragma unroll
                for (int ns = 0; ns < 8; ns++) {
                    int j = ns >> 1, sel = ns & 1;
                    MMA_F16(c[mi][ns], ah[mi], bh[j][sel], bh[j][sel + 2]);
                }
        }

        if (more) {
            *(uint4*)(smem + stN + bDst + 0)  = cvt8(rb[0], rb[1]);
            *(uint4*)(smem + stN + bDst + 16) = cvt8(rb[2], rb[3]);
        }
    }

    #pragma unroll
    for (int mi = 0; mi < 2; mi++) {
        int lr0 = m0 + wm * 32 + mi * 16 + (lane >> 2);
        #pragma unroll
        for (int half_ = 0; half_ < 2; half_++) {
            int lr = lr0 + half_ * 8;
            float s = 1.f;
            if (SCALEMODE == 2) s = rscale[lr];
            float* cp = C + (size_t)lr * Ntot + n0 + wn * 64 + (lane & 3) * 2;
            #pragma unroll
            for (int ns = 0; ns < 8; ns++) {
                float2 v = make_float2(c[mi][ns][half_ * 2 + 0] * s,
                                       c[mi][ns][half_ * 2 + 1] * s);
                *(float2*)(cp + ns * 8) = v;
            }
        }
    }
}

// ================= launch =================
extern "C" void kernel_launch(void* const* d_in, const int* in_sizes, int n_in,
                              void* d_out, int out_size) {
    const float* x      = (const float*)d_in[0];
    const float* gate_w = (const float*)d_in[1];
    const float* sgw    = (const float*)d_in[2];
    const float* w13    = (const float*)d_in[3];
    const float* w2     = (const float*)d_in[4];
    const float* segu   = (const float*)d_in[5];
    const float* sedw   = (const float*)d_in[6];
    float* out = (float*)d_out;

    int M = in_sizes[0] / H;   // 1024

    float *gu_p, *hsh_p, *gur_p, *hr_p, *y_p, *sig_p;
    __half *x16_p;
    cudaGetSymbolAddress((void**)&gu_p,  g_gu);
    cudaGetSymbolAddress((void**)&hsh_p, g_hsh);
    cudaGetSymbolAddress((void**)&gur_p, g_gur);
    cudaGetSymbolAddress((void**)&hr_p,  g_hr);
    cudaGetSymbolAddress((void**)&y_p,   g_y);
    cudaGetSymbolAddress((void**)&sig_p, g_sig);
    cudaGetSymbolAddress((void**)&x16_p, g_x16);

    const int SMEM_M128 = 2 * (256 * ROWB);   // 73728
    const int SMEM_M64  = 2 * (192 * ROWB);   // 55296

    cudaFuncSetAttribute(dense_gemm<0>,     cudaFuncAttributeMaxDynamicSharedMemorySize, D_SMEM);
    cudaFuncSetAttribute(mma_gemm<2,0,0,2>, cudaFuncAttributeMaxDynamicSharedMemorySize, SMEM_M128);
    cudaFuncSetAttribute(mma_gemm<1,1,1,0>, cudaFuncAttributeMaxDynamicSharedMemorySize, SMEM_M64);
    cudaFuncSetAttribute(mma_gemm<1,0,1,1>, cudaFuncAttributeMaxDynamicSharedMemorySize, SMEM_M64);

    // routing pipeline
    zero_counts_kernel<<<1, 64>>>();
    router_kernel<<<M, 256>>>(x, gate_w, sgw);
    scan_kernel<<<1, 32>>>();
    fill_kernel<<<(M + 255) / 256, 256>>>(M);
    x16_kernel<<<(M * H + 255) / 256, 256>>>(x, M * H);

    // shared expert: gate_up on the measured-best R7 dense engine
    dense_gemm<0><<<dim3(ISH2 / 256, M / 128), 512, D_SMEM>>>(
        x16_p, H, segu, gu_p, ISH2, H, nullptr);
    silu_mul_kernel<<<1024, 256>>>(gu_p, hsh_p, M, ISH, ISH2);
    // shared expert: down proj on champion engine (128-row tiles, scaled)
    mma_gemm<2,0,0,2><<<dim3(H / 128, M / 128), 512, SMEM_M128>>>(
        hsh_p, ISH, sedw, 0, out, H, ISH, sig_p);

    // routed experts on champion engine (64-row m-tiles)
    int mtiles = M / 64;
    mma_gemm<1,1,1,0><<<dim3(I2 / 128, mtiles, E), 512, SMEM_M64>>>(
        x, H, w13, (size_t)I2 * H, gur_p, I2, H, nullptr);
    silu_mul_kernel<<<1024, 256>>>(gur_p, hr_p, M * TOPK, II, I2);
    mma_gemm<1,0,1,1><<<dim3(H / 128, mtiles, E), 512, SMEM_M64>>>(
        hr_p, II, w2, (size_t)H * II, y_p, H, II, nullptr);

    // deterministic per-token combine
    combine_kernel<<<M, 256>>>(out);
}

// round 16
// speedup vs baseline: 1.6234x; 1.0497x over previous
#include <cuda_runtime.h>
#include <cuda_fp16.h>
#include <math.h>
#include <stdint.h>
#include <string.h>

// ================= problem constants =================
#define H     2048
#define E     60
#define II    1408
#define I2    2816
#define ISH   5632
#define ISH2  11264
#define TOPK  4
#define MAXM  1024
#define MAXSLOTS (MAXM*TOPK)

// ================= device scratch =================
static __device__ float  g_gu  [MAXM * ISH2];     // dense gate_up out (fp32)
static __device__ float  g_gur [MAXSLOTS * I2];   // routed gate_up out (fp32)
static __device__ __half g_hsh [MAXM * ISH];      // silu(gate)*up shared (fp16)
static __device__ __half g_hr  [MAXSLOTS * II];   // silu(gate)*up routed (fp16)
static __device__ float  g_y   [MAXSLOTS * H];
static __device__ __half g_x16 [MAXM * H];
static __device__ float  g_sig [MAXM];
static __device__ int    g_cnt [E];
static __device__ int    g_off [E];
static __device__ int    g_cur [E];
static __device__ int    g_slot_token[MAXSLOTS];
static __device__ float  g_slot_w    [MAXSLOTS];
static __device__ int    g_slot_of   [MAXM * TOPK];
static __device__ int    g_tk_e      [MAXM * TOPK];
static __device__ float  g_tk_w      [MAXM * TOPK];

// ================= small kernels =================
__global__ void zero_counts_kernel() {
    int t = threadIdx.x;
    if (t < E) g_cnt[t] = 0;
}

__global__ void x16_kernel(const float* __restrict__ x, int n) {
    int i = blockIdx.x * blockDim.x + threadIdx.x;
    if (i < n) g_x16[i] = __float2half(x[i]);
}

__global__ void router_kernel(const float* __restrict__ x,
                              const float* __restrict__ gate_w,
                              const float* __restrict__ sgw) {
    __shared__ float xs[H];
    __shared__ float logits[E + 1];
    int m = blockIdx.x;
    const float* xr = x + (size_t)m * H;
    for (int i = threadIdx.x; i < H; i += blockDim.x) xs[i] = xr[i];
    __syncthreads();

    int wid = threadIdx.x >> 5, lane = threadIdx.x & 31;
    for (int e = wid; e <= E; e += 8) {
        const float* wr = (e < E) ? (gate_w + (size_t)e * H) : sgw;
        float acc = 0.f;
        for (int k = lane; k < H; k += 32) acc += xs[k] * wr[k];
        #pragma unroll
        for (int o = 16; o; o >>= 1) acc += __shfl_xor_sync(0xffffffffu, acc, o);
        if (lane == 0) logits[e] = acc;
    }
    __syncthreads();

    if (threadIdx.x == 0) {
        g_sig[m] = 1.f / (1.f + expf(-logits[E]));
        float mx = -1e30f;
        for (int e = 0; e < E; e++) mx = fmaxf(mx, logits[e]);
        float sum = 0.f;
        for (int e = 0; e < E; e++) { float p = expf(logits[e] - mx); logits[e] = p; sum += p; }
        float inv = 1.f / sum;
        for (int k = 0; k < TOPK; k++) {
            int best = 0; float bv = -1.f;
            for (int e = 0; e < E; e++) { float v = logits[e]; if (v > bv) { bv = v; best = e; } }
            logits[best] = -2.f;
            g_tk_e[m * TOPK + k] = best;
            g_tk_w[m * TOPK + k] = bv * inv;
            atomicAdd(&g_cnt[best], 1);
        }
    }
}

__global__ void scan_kernel() {
    if (threadIdx.x == 0) {
        int s = 0;
        for (int e = 0; e < E; e++) { g_off[e] = s; s += g_cnt[e]; g_cur[e] = 0; }
    }
}

__global__ void fill_kernel(int M) {
    int m = blockIdx.x * blockDim.x + threadIdx.x;
    if (m >= M) return;
    for (int k = 0; k < TOPK; k++) {
        int e = g_tk_e[m * TOPK + k];
        int pos = atomicAdd(&g_cur[e], 1);
        int slot = g_off[e] + pos;
        g_slot_token[slot] = m;
        g_slot_w[slot] = g_tk_w[m * TOPK + k];
        g_slot_of[m * TOPK + k] = slot;
    }
}

__device__ __forceinline__ float silu_f(float v) { return v / (1.f + expf(-v)); }

// silu-and-mul, fp32 in -> fp16 out (A operand of the next GEMM; it would be
// fp16-rounded there anyway, so this adds zero error).
__global__ void silu_mul_kernel(const float* __restrict__ gu, __half* __restrict__ h,
                                int rows, int half_, int full) {
    int total = rows * half_;
    for (int idx = blockIdx.x * blockDim.x + threadIdx.x; idx < total;
         idx += gridDim.x * blockDim.x) {
        int r = idx / half_, i = idx - r * half_;
        float g = gu[(size_t)r * full + i];
        float u = gu[(size_t)r * full + half_ + i];
        h[(size_t)r * half_ + i] = __float2half(silu_f(g) * u);
    }
}

__global__ void combine_kernel(float* __restrict__ out) {
    int m = blockIdx.x;
    int s0 = g_slot_of[m * TOPK + 0];
    int s1 = g_slot_of[m * TOPK + 1];
    int s2 = g_slot_of[m * TOPK + 2];
    int s3 = g_slot_of[m * TOPK + 3];
    for (int hcol = threadIdx.x; hcol < H; hcol += blockDim.x) {
        float v = out[(size_t)m * H + hcol];
        v += g_y[(size_t)s0 * H + hcol];
        v += g_y[(size_t)s1 * H + hcol];
        v += g_y[(size_t)s2 * H + hcol];
        v += g_y[(size_t)s3 * H + hcol];
        out[(size_t)m * H + hcol] = v;
    }
}

// ================= shared GEMM helpers =================
__device__ __forceinline__ uint32_t smem_u32(const void* p) {
    uint32_t a;
    asm("{ .reg .u64 t; cvta.to.shared.u64 t, %1; cvt.u32.u64 %0, t; }" : "=r"(a) : "l"(p));
    return a;
}
__device__ __forceinline__ uint32_t h2u(__half2 h) {
    uint32_t u; memcpy(&u, &h, 4); return u;
}

#define CP_ASYNC16(dst, src, srcsize) \
    asm volatile("cp.async.cg.shared.global [%0], [%1], 16, %2;" \
        :: "r"(dst), "l"(src), "r"(srcsize) : "memory")
#define CP_COMMIT() asm volatile("cp.async.commit_group;" ::: "memory")
#define CP_WAIT0()  asm volatile("cp.async.wait_group 0;" ::: "memory")

#define LDSM4(r, addr) \
    asm volatile("ldmatrix.sync.aligned.m8n8.x4.shared.b16 {%0,%1,%2,%3}, [%4];" \
        : "=r"((r)[0]), "=r"((r)[1]), "=r"((r)[2]), "=r"((r)[3]) : "r"(addr))

#define MMA_F16(c, a, b0, b1) \
    asm volatile("mma.sync.aligned.m16n8k16.row.col.f32.f16.f16.f32 " \
        "{%0,%1,%2,%3}, {%4,%5,%6,%7}, {%8,%9}, {%0,%1,%2,%3};" \
        : "+f"((c)[0]), "+f"((c)[1]), "+f"((c)[2]), "+f"((c)[3]) \
        : "r"((a)[0]), "r"((a)[1]), "r"((a)[2]), "r"((a)[3]), "r"(b0), "r"(b1))

__device__ __forceinline__ uint4 cvt8(float4 v0, float4 v1) {
    __half2 h0 = __floats2half2_rn(v0.x, v0.y);
    __half2 h1 = __floats2half2_rn(v0.z, v0.w);
    __half2 h2 = __floats2half2_rn(v1.x, v1.y);
    __half2 h3 = __floats2half2_rn(v1.z, v1.w);
    return make_uint4(h2u(h0), h2u(h1), h2u(h2), h2u(h3));
}

// ===== CHAMPION engine (R15) with fp16 A, register-staged =================
// Tile MTILE x 128 (MTILE = MI*64), KC=64, 512 threads (16 warps 4m x 4n,
// warp tile (MI*16) x 32), 2-stage ring, one barrier/chunk, loads hoisted
// above the barrier. A fp16 gmem -> LDG.128 regs -> STS (no cvt);
// B fp32 gmem -> LDG -> cvt -> STS.
#define KC       64
#define ROWB     144                 // 64 halves + 8 pad

template<int MI, int GATHER, int ROUTED, int SCALEMODE>
__global__ void __launch_bounds__(512, 1) mma_gemm(
    const __half* __restrict__ A, int lda,
    const float* __restrict__ Bbase, size_t strideB,
    float* __restrict__ C, int Ntot, int K,
    const float* __restrict__ rscale)
{
    constexpr int MTILE   = MI * 64;
    constexpr int A_BYTES = MTILE * ROWB;
    constexpr int STAGE   = (MTILE + 128) * ROWB;

    extern __shared__ char smem[];
    int cnt = 0x3fffffff, off = 0, m0 = blockIdx.y * MTILE;
    const float* Bp = Bbase;
    if (ROUTED) {
        int e = blockIdx.z;
        cnt = g_cnt[e];
        if (m0 >= cnt) return;
        off = g_off[e];
        Bp += (size_t)e * strideB;
    }
    int n0 = blockIdx.x * 128;
    int tid = threadIdx.x;

    // ---- A loader mapping (fp16 halves) ----
    // MI=2: thread covers 16 contiguous halves (32B); MI=1: 8 halves (16B).
    int rA, cA;
    if (MI == 2) { rA = tid >> 2; cA = (tid & 3) * 16; }
    else         { rA = tid >> 3; cA = (tid & 7) * 8; }
    long arow;
    if (!ROUTED) arow = m0 + rA;
    else {
        int l = m0 + rA;
        arow = (l < cnt) ? (GATHER ? (long)g_slot_token[off + l] : (long)(off + l)) : -1;
    }
    bool av = (arow >= 0);
    const __half* apf = A + (size_t)(av ? arow : 0) * lda + cA;
    uint32_t swA0 = (uint32_t)(rA * ROWB + cA * 2);

    // ---- B loader mapping (fp32) ----
    int rB = tid >> 2, cqB = (tid & 3) << 3;
    const float* bpf = Bp + (size_t)(n0 + rB) * K + cqB;
    uint32_t swB0 = (uint32_t)(A_BYTES + rB * ROWB + cqB * 2);
    uint32_t swB1 = swB0 + 64;

    uint32_t sm0 = smem_u32(smem);

    // ---- ldmatrix bases ----
    int lane = tid & 31, wid = tid >> 5;
    int wm = wid & 3, wn = wid >> 2;
    uint32_t lmoff = (uint32_t)((lane & 15) * ROWB + (lane >> 4) * 16);
    uint32_t aBase = sm0 + (uint32_t)(wm * (MI * 16) * ROWB) + lmoff;
    uint32_t bBase = sm0 + A_BYTES + (uint32_t)(wn * 32 * ROWB) + lmoff;

    float c[MI][4][4];
    #pragma unroll
    for (int i = 0; i < MI; i++)
        #pragma unroll
        for (int j = 0; j < 4; j++)
            #pragma unroll
            for (int q = 0; q < 4; q++) c[i][j][q] = 0.f;

    int KT = K / KC;
    const uint4 zu4 = make_uint4(0u, 0u, 0u, 0u);
    uint4 ra0, ra1;
    float4 rb[4];

    // prologue: chunk 0 -> regs -> stage 0
    ra0 = av ? *(const uint4*)(apf) : zu4;
    if (MI == 2) ra1 = av ? *(const uint4*)(apf + 8) : zu4;
    #pragma unroll
    for (int q = 0; q < 2; q++) {
        rb[2*q+0] = *(const float4*)(bpf + 32*q + 0);
        rb[2*q+1] = *(const float4*)(bpf + 32*q + 4);
    }
    {
        *(uint4*)(smem + swA0) = ra0;
        if (MI == 2) *(uint4*)(smem + swA0 + 16) = ra1;
        *(uint4*)(smem + swB0) = cvt8(rb[0], rb[1]);
        *(uint4*)(smem + swB1) = cvt8(rb[2], rb[3]);
    }

    for (int kt = 0; kt < KT; kt++) {
        bool more = (kt + 1 < KT);
        // loads hoisted above the barrier: in flight while warp waits
        if (more) {
            const __half* ap = apf + (kt + 1) * KC;
            const float*  bp = bpf + (kt + 1) * KC;
            ra0 = av ? *(const uint4*)(ap) : zu4;
            if (MI == 2) ra1 = av ? *(const uint4*)(ap + 8) : zu4;
            #pragma unroll
            for (int q = 0; q < 2; q++) {
                rb[2*q+0] = *(const float4*)(bp + 32*q + 0);
                rb[2*q+1] = *(const float4*)(bp + 32*q + 4);
            }
        }
        __syncthreads();

        // MMAs on current stage
        uint32_t st = (uint32_t)(kt & 1) * STAGE;
        uint32_t ab = aBase + st, bb = bBase + st;
        #pragma unroll
        for (int kk = 0; kk < 4; kk++) {
            uint32_t ah[MI][4], bh[2][4];
            #pragma unroll
            for (int mi = 0; mi < MI; mi++)
                LDSM4(ah[mi], ab + mi * (16 * ROWB) + kk * 32);
            #pragma unroll
            for (int j = 0; j < 2; j++)
                LDSM4(bh[j], bb + j * (16 * ROWB) + kk * 32);
            #pragma unroll
            for (int mi = 0; mi < MI; mi++) {
                #pragma unroll
                for (int ns = 0; ns < 4; ns++) {
                    int j = ns >> 1, sel = ns & 1;
                    MMA_F16(c[mi][ns], ah[mi], bh[j][sel], bh[j][sel + 2]);
                }
            }
        }

        // store chunk kt+1 into the other stage
        if (more) {
            char* sb = smem + ((kt + 1) & 1) * STAGE;
            *(uint4*)(sb + swA0) = ra0;
            if (MI == 2) *(uint4*)(sb + swA0 + 16) = ra1;
            *(uint4*)(sb + swB0) = cvt8(rb[0], rb[1]);
            *(uint4*)(sb + swB1) = cvt8(rb[2], rb[3]);
        }
    }

    // ---- epilogue ----
    #pragma unroll
    for (int mi = 0; mi < MI; mi++) {
        int lr0 = m0 + wm * (MI * 16) + mi * 16 + (lane >> 2);
        #pragma unroll
        for (int half_ = 0; half_ < 2; half_++) {
            int lr = lr0 + half_ * 8;
            bool valid = !ROUTED || (lr < cnt);
            if (!valid) continue;
            int orow = ROUTED ? (off + lr) : lr;
            float s = 1.f;
            if (SCALEMODE == 1) s = g_slot_w[off + lr];
            if (SCALEMODE == 2) s = rscale[lr];
            float* cp = C + (size_t)orow * Ntot + n0 + wn * 32 + (lane & 3) * 2;
            #pragma unroll
            for (int ns = 0; ns < 4; ns++) {
                float2 v = make_float2(c[mi][ns][half_ * 2 + 0] * s,
                                       c[mi][ns][half_ * 2 + 1] * s);
                *(float2*)(cp + ns * 8) = v;
            }
        }
    }
}

// ===== R7 dense engine (measured 277us on dense1): 128x256, KC=32 ==========
#define DROWB   80
#define D_AB    (128 * DROWB)
#define D_STG   (D_AB + 256 * DROWB)
#define D_SMEM  (2 * D_STG)

template<int SCALEMODE>
__global__ void __launch_bounds__(512, 1) dense_gemm(
    const __half* __restrict__ A, int lda,
    const float* __restrict__ B,
    float* __restrict__ C, int Ntot, int K,
    const float* __restrict__ rscale)
{
    extern __shared__ char smem[];
    int m0 = blockIdx.y * 128;
    int n0 = blockIdx.x * 256;
    int tid = threadIdx.x;

    int rA = tid >> 2;
    int pA = (tid & 3) << 4;
    const char* aSrc = (const char*)(A + (size_t)(m0 + rA) * lda) + pA;
    uint32_t aDst = (uint32_t)(rA * DROWB + pA);

    int rB = tid >> 1, hB = tid & 1;
    const float* bpf = B + (size_t)(n0 + rB) * K + hB * 16;
    uint32_t bDst = (uint32_t)(D_AB + rB * DROWB + hB * 32);

    uint32_t sm0 = smem_u32(smem);
    int lane = tid & 31, wid = tid >> 5;
    int wm = wid & 3, wn = wid >> 2;
    uint32_t lmoff = (uint32_t)((lane & 15) * DROWB + (lane >> 4) * 16);
    uint32_t aBase = sm0 + (uint32_t)(wm * 32 * DROWB) + lmoff;
    uint32_t bBase = sm0 + D_AB + (uint32_t)(wn * 64 * DROWB) + lmoff;

    float c[2][8][4];
    #pragma unroll
    for (int i = 0; i < 2; i++)
        #pragma unroll
        for (int j = 0; j < 8; j++)
            #pragma unroll
            for (int q = 0; q < 4; q++) c[i][j][q] = 0.f;

    int KT = K / 32;
    float4 rb[4];

    CP_ASYNC16(sm0 + aDst, aSrc, 16);
    CP_COMMIT();
    #pragma unroll
    for (int q = 0; q < 4; q++) rb[q] = *(const float4*)(bpf + 4 * q);
    *(uint4*)(smem + bDst + 0)  = cvt8(rb[0], rb[1]);
    *(uint4*)(smem + bDst + 16) = cvt8(rb[2], rb[3]);

    for (int kt = 0; kt < KT; kt++) {
        CP_WAIT0();
        __syncthreads();
        bool more = (kt + 1 < KT);
        uint32_t stN = (uint32_t)((kt + 1) & 1) * D_STG;
        if (more) {
            CP_ASYNC16(sm0 + stN + aDst, aSrc + (size_t)(kt + 1) * 64, 16);
            CP_COMMIT();
            const float* bp = bpf + (kt + 1) * 32;
            #pragma unroll
            for (int q = 0; q < 4; q++) rb[q] = *(const float4*)(bp + 4 * q);
        }

        uint32_t st = (uint32_t)(kt & 1) * D_STG;
        uint32_t ab = aBase + st, bb = bBase + st;
        #pragma unroll
        for (int kk = 0; kk < 2; kk++) {
            uint32_t ah[2][4], bh[4][4];
            #pragma unroll
            for (int mi = 0; mi < 2; mi++)
                LDSM4(ah[mi], ab + mi * (16 * DROWB) + kk * 32);
            #pragma unroll
            for (int j = 0; j < 4; j++)
                LDSM4(bh[j], bb + j * (16 * DROWB) + kk * 32);
            #pragma unroll
            for (int mi = 0; mi < 2; mi++)
                #pragma unroll
                for (int ns = 0; ns < 8; ns++) {
                    int j = ns >> 1, sel = ns & 1;
                    MMA_F16(c[mi][ns], ah[mi], bh[j][sel], bh[j][sel + 2]);
                }
        }

        if (more) {
            *(uint4*)(smem + stN + bDst + 0)  = cvt8(rb[0], rb[1]);
            *(uint4*)(smem + stN + bDst + 16) = cvt8(rb[2], rb[3]);
        }
    }

    #pragma unroll
    for (int mi = 0; mi < 2; mi++) {
        int lr0 = m0 + wm * 32 + mi * 16 + (lane >> 2);
        #pragma unroll
        for (int half_ = 0; half_ < 2; half_++) {
            int lr = lr0 + half_ * 8;
            float s = 1.f;
            if (SCALEMODE == 2) s = rscale[lr];
            float* cp = C + (size_t)lr * Ntot + n0 + wn * 64 + (lane & 3) * 2;
            #pragma unroll
            for (int ns = 0; ns < 8; ns++) {
                float2 v = make_float2(c[mi][ns][half_ * 2 + 0] * s,
                                       c[mi][ns][half_ * 2 + 1] * s);
                *(float2*)(cp + ns * 8) = v;
            }
        }
    }
}

// ================= launch =================
extern "C" void kernel_launch(void* const* d_in, const int* in_sizes, int n_in,
                              void* d_out, int out_size) {
    const float* x      = (const float*)d_in[0];
    const float* gate_w = (const float*)d_in[1];
    const float* sgw    = (const float*)d_in[2];
    const float* w13    = (const float*)d_in[3];
    const float* w2     = (const float*)d_in[4];
    const float* segu   = (const float*)d_in[5];
    const float* sedw   = (const float*)d_in[6];
    float* out = (float*)d_out;

    int M = in_sizes[0] / H;   // 1024

    float *gu_p, *gur_p, *y_p, *sig_p;
    __half *hsh_p, *hr_p, *x16_p;
    cudaGetSymbolAddress((void**)&gu_p,  g_gu);
    cudaGetSymbolAddress((void**)&gur_p, g_gur);
    cudaGetSymbolAddress((void**)&hsh_p, g_hsh);
    cudaGetSymbolAddress((void**)&hr_p,  g_hr);
    cudaGetSymbolAddress((void**)&y_p,   g_y);
    cudaGetSymbolAddress((void**)&sig_p, g_sig);
    cudaGetSymbolAddress((void**)&x16_p, g_x16);

    const int SMEM_M128 = 2 * (256 * ROWB);   // 73728
    const int SMEM_M64  = 2 * (192 * ROWB);   // 55296

    cudaFuncSetAttribute(dense_gemm<0>,     cudaFuncAttributeMaxDynamicSharedMemorySize, D_SMEM);
    cudaFuncSetAttribute(mma_gemm<2,0,0,2>, cudaFuncAttributeMaxDynamicSharedMemorySize, SMEM_M128);
    cudaFuncSetAttribute(mma_gemm<1,1,1,0>, cudaFuncAttributeMaxDynamicSharedMemorySize, SMEM_M64);
    cudaFuncSetAttribute(mma_gemm<1,0,1,1>, cudaFuncAttributeMaxDynamicSharedMemorySize, SMEM_M64);

    // routing pipeline
    zero_counts_kernel<<<1, 64>>>();
    router_kernel<<<M, 256>>>(x, gate_w, sgw);
    scan_kernel<<<1, 32>>>();
    fill_kernel<<<(M + 255) / 256, 256>>>(M);
    x16_kernel<<<(M * H + 255) / 256, 256>>>(x, M * H);

    // shared expert: gate_up on measured-best R7 dense engine
    dense_gemm<0><<<dim3(ISH2 / 256, M / 128), 512, D_SMEM>>>(
        x16_p, H, segu, gu_p, ISH2, H, nullptr);
    silu_mul_kernel<<<1024, 256>>>(gu_p, hsh_p, M, ISH, ISH2);
    // shared expert: down proj on champion engine (fp16 A, scaled)
    mma_gemm<2,0,0,2><<<dim3(H / 128, M / 128), 512, SMEM_M128>>>(
        hsh_p, ISH, sedw, 0, out, H, ISH, sig_p);

    // routed experts on champion engine (fp16 A, 64-row m-tiles)
    int mtiles = M / 64;
    mma_gemm<1,1,1,0><<<dim3(I2 / 128, mtiles, E), 512, SMEM_M64>>>(
        x16_p, H, w13, (size_t)I2 * H, gur_p, I2, H, nullptr);
    silu_mul_kernel<<<1024, 256>>>(gur_p, hr_p, M * TOPK, II, I2);
    mma_gemm<1,0,1,1><<<dim3(H / 128, mtiles, E), 512, SMEM_M64>>>(
        hr_p, II, w2, (size_t)H * II, y_p, H, II, nullptr);

    // deterministic per-token combine
    combine_kernel<<<M, 256>>>(out);
}

// round 17
// speedup vs baseline: 1.8992x; 1.1699x over previous
#include <cuda_runtime.h>
#include <cuda_fp16.h>
#include <math.h>
#include <stdint.h>
#include <string.h>

// ================= problem constants =================
#define H     2048
#define E     60
#define II    1408
#define I2    2816
#define ISH   5632
#define ISH2  11264
#define TOPK  4
#define MAXM  1024
#define MAXSLOTS (MAXM*TOPK)

// ================= device scratch =================
static __device__ float  g_gu  [MAXM * ISH2];     // dense gate_up out (fp32)
static __device__ float  g_gur [MAXSLOTS * I2];   // routed gate_up out (fp32)
static __device__ __half g_hsh [MAXM * ISH];      // silu(gate)*up shared (fp16)
static __device__ __half g_hr  [MAXSLOTS * II];   // silu(gate)*up routed (fp16)
static __device__ float  g_y   [MAXSLOTS * H];
static __device__ __half g_x16 [MAXM * H];
static __device__ float  g_sig [MAXM];
static __device__ int    g_cnt [E];
static __device__ int    g_off [E];
static __device__ int    g_cur [E];
static __device__ int    g_slot_token[MAXSLOTS];
static __device__ float  g_slot_w    [MAXSLOTS];
static __device__ int    g_slot_of   [MAXM * TOPK];
static __device__ int    g_tk_e      [MAXM * TOPK];
static __device__ float  g_tk_w      [MAXM * TOPK];

// ================= small kernels =================
__global__ void zero_counts_kernel() {
    int t = threadIdx.x;
    if (t < E) g_cnt[t] = 0;
}

__global__ void x16_kernel(const float* __restrict__ x, int n) {
    int i = blockIdx.x * blockDim.x + threadIdx.x;
    if (i < n) g_x16[i] = __float2half(x[i]);
}

__global__ void router_kernel(const float* __restrict__ x,
                              const float* __restrict__ gate_w,
                              const float* __restrict__ sgw) {
    __shared__ float xs[H];
    __shared__ float logits[E + 1];
    int m = blockIdx.x;
    const float* xr = x + (size_t)m * H;
    for (int i = threadIdx.x; i < H; i += blockDim.x) xs[i] = xr[i];
    __syncthreads();

    int wid = threadIdx.x >> 5, lane = threadIdx.x & 31;
    for (int e = wid; e <= E; e += 8) {
        const float* wr = (e < E) ? (gate_w + (size_t)e * H) : sgw;
        float acc = 0.f;
        for (int k = lane; k < H; k += 32) acc += xs[k] * wr[k];
        #pragma unroll
        for (int o = 16; o; o >>= 1) acc += __shfl_xor_sync(0xffffffffu, acc, o);
        if (lane == 0) logits[e] = acc;
    }
    __syncthreads();

    if (threadIdx.x == 0) {
        g_sig[m] = 1.f / (1.f + expf(-logits[E]));
        float mx = -1e30f;
        for (int e = 0; e < E; e++) mx = fmaxf(mx, logits[e]);
        float sum = 0.f;
        for (int e = 0; e < E; e++) { float p = expf(logits[e] - mx); logits[e] = p; sum += p; }
        float inv = 1.f / sum;
        for (int k = 0; k < TOPK; k++) {
            int best = 0; float bv = -1.f;
            for (int e = 0; e < E; e++) { float v = logits[e]; if (v > bv) { bv = v; best = e; } }
            logits[best] = -2.f;
            g_tk_e[m * TOPK + k] = best;
            g_tk_w[m * TOPK + k] = bv * inv;
            atomicAdd(&g_cnt[best], 1);
        }
    }
}

__global__ void scan_kernel() {
    if (threadIdx.x == 0) {
        int s = 0;
        for (int e = 0; e < E; e++) { g_off[e] = s; s += g_cnt[e]; g_cur[e] = 0; }
    }
}

__global__ void fill_kernel(int M) {
    int m = blockIdx.x * blockDim.x + threadIdx.x;
    if (m >= M) return;
    for (int k = 0; k < TOPK; k++) {
        int e = g_tk_e[m * TOPK + k];
        int pos = atomicAdd(&g_cur[e], 1);
        int slot = g_off[e] + pos;
        g_slot_token[slot] = m;
        g_slot_w[slot] = g_tk_w[m * TOPK + k];
        g_slot_of[m * TOPK + k] = slot;
    }
}

__device__ __forceinline__ float silu_f(float v) { return v / (1.f + expf(-v)); }

// silu-and-mul, fp32 in -> fp16 out (A operand of the next GEMM).
__global__ void silu_mul_kernel(const float* __restrict__ gu, __half* __restrict__ h,
                                int rows, int half_, int full) {
    int total = rows * half_;
    for (int idx = blockIdx.x * blockDim.x + threadIdx.x; idx < total;
         idx += gridDim.x * blockDim.x) {
        int r = idx / half_, i = idx - r * half_;
        float g = gu[(size_t)r * full + i];
        float u = gu[(size_t)r * full + half_ + i];
        h[(size_t)r * half_ + i] = __float2half(silu_f(g) * u);
    }
}

__global__ void combine_kernel(float* __restrict__ out) {
    int m = blockIdx.x;
    int s0 = g_slot_of[m * TOPK + 0];
    int s1 = g_slot_of[m * TOPK + 1];
    int s2 = g_slot_of[m * TOPK + 2];
    int s3 = g_slot_of[m * TOPK + 3];
    for (int hcol = threadIdx.x; hcol < H; hcol += blockDim.x) {
        float v = out[(size_t)m * H + hcol];
        v += g_y[(size_t)s0 * H + hcol];
        v += g_y[(size_t)s1 * H + hcol];
        v += g_y[(size_t)s2 * H + hcol];
        v += g_y[(size_t)s3 * H + hcol];
        out[(size_t)m * H + hcol] = v;
    }
}

// ================= shared GEMM helpers =================
__device__ __forceinline__ uint32_t smem_u32(const void* p) {
    uint32_t a;
    asm("{ .reg .u64 t; cvta.to.shared.u64 t, %1; cvt.u32.u64 %0, t; }" : "=r"(a) : "l"(p));
    return a;
}
__device__ __forceinline__ uint32_t h2u(__half2 h) {
    uint32_t u; memcpy(&u, &h, 4); return u;
}

#define CP_ASYNC16(dst, src, srcsize) \
    asm volatile("cp.async.cg.shared.global [%0], [%1], 16, %2;" \
        :: "r"(dst), "l"(src), "r"(srcsize) : "memory")
#define CP_COMMIT() asm volatile("cp.async.commit_group;" ::: "memory")
#define CP_WAIT0()  asm volatile("cp.async.wait_group 0;" ::: "memory")

#define LDSM4(r, addr) \
    asm volatile("ldmatrix.sync.aligned.m8n8.x4.shared.b16 {%0,%1,%2,%3}, [%4];" \
        : "=r"((r)[0]), "=r"((r)[1]), "=r"((r)[2]), "=r"((r)[3]) : "r"(addr))

#define MMA_F16(c, a, b0, b1) \
    asm volatile("mma.sync.aligned.m16n8k16.row.col.f32.f16.f16.f32 " \
        "{%0,%1,%2,%3}, {%4,%5,%6,%7}, {%8,%9}, {%0,%1,%2,%3};" \
        : "+f"((c)[0]), "+f"((c)[1]), "+f"((c)[2]), "+f"((c)[3]) \
        : "r"((a)[0]), "r"((a)[1]), "r"((a)[2]), "r"((a)[3]), "r"(b0), "r"(b1))

__device__ __forceinline__ uint4 cvt8(float4 v0, float4 v1) {
    __half2 h0 = __floats2half2_rn(v0.x, v0.y);
    __half2 h1 = __floats2half2_rn(v0.z, v0.w);
    __half2 h2 = __floats2half2_rn(v1.x, v1.y);
    __half2 h3 = __floats2half2_rn(v1.z, v1.w);
    return make_uint4(h2u(h0), h2u(h1), h2u(h2), h2u(h3));
}

// ===== CHAMPION engine (R16): fp16 A reg-staged, fp32 B reg-staged =========
// Tile MTILE x 128 (MTILE = MI*64), KC=64, 512 threads (16 warps 4m x 4n,
// warp tile (MI*16) x 32), 2-stage ring, one barrier/chunk, loads hoisted
// above the barrier.
#define KC       64
#define ROWB     144                 // 64 halves + 8 pad

template<int MI, int GATHER, int ROUTED, int SCALEMODE>
__global__ void __launch_bounds__(512, 1) mma_gemm(
    const __half* __restrict__ A, int lda,
    const float* __restrict__ Bbase, size_t strideB,
    float* __restrict__ C, int Ntot, int K,
    const float* __restrict__ rscale)
{
    constexpr int MTILE   = MI * 64;
    constexpr int A_BYTES = MTILE * ROWB;
    constexpr int STAGE   = (MTILE + 128) * ROWB;

    extern __shared__ char smem[];
    int cnt = 0x3fffffff, off = 0, m0 = blockIdx.y * MTILE;
    const float* Bp = Bbase;
    if (ROUTED) {
        int e = blockIdx.z;
        cnt = g_cnt[e];
        if (m0 >= cnt) return;
        off = g_off[e];
        Bp += (size_t)e * strideB;
    }
    int n0 = blockIdx.x * 128;
    int tid = threadIdx.x;

    // ---- A loader mapping (fp16 halves) ----
    int rA, cA;
    if (MI == 2) { rA = tid >> 2; cA = (tid & 3) * 16; }
    else         { rA = tid >> 3; cA = (tid & 7) * 8; }
    long arow;
    if (!ROUTED) arow = m0 + rA;
    else {
        int l = m0 + rA;
        arow = (l < cnt) ? (GATHER ? (long)g_slot_token[off + l] : (long)(off + l)) : -1;
    }
    bool av = (arow >= 0);
    const __half* apf = A + (size_t)(av ? arow : 0) * lda + cA;
    uint32_t swA0 = (uint32_t)(rA * ROWB + cA * 2);

    // ---- B loader mapping (fp32) ----
    int rB = tid >> 2, cqB = (tid & 3) << 3;
    const float* bpf = Bp + (size_t)(n0 + rB) * K + cqB;
    uint32_t swB0 = (uint32_t)(A_BYTES + rB * ROWB + cqB * 2);
    uint32_t swB1 = swB0 + 64;

    uint32_t sm0 = smem_u32(smem);

    // ---- ldmatrix bases ----
    int lane = tid & 31, wid = tid >> 5;
    int wm = wid & 3, wn = wid >> 2;
    uint32_t lmoff = (uint32_t)((lane & 15) * ROWB + (lane >> 4) * 16);
    uint32_t aBase = sm0 + (uint32_t)(wm * (MI * 16) * ROWB) + lmoff;
    uint32_t bBase = sm0 + A_BYTES + (uint32_t)(wn * 32 * ROWB) + lmoff;

    float c[MI][4][4];
    #pragma unroll
    for (int i = 0; i < MI; i++)
        #pragma unroll
        for (int j = 0; j < 4; j++)
            #pragma unroll
            for (int q = 0; q < 4; q++) c[i][j][q] = 0.f;

    int KT = K / KC;
    const uint4 zu4 = make_uint4(0u, 0u, 0u, 0u);
    uint4 ra0, ra1;
    float4 rb[4];

    // prologue: chunk 0 -> regs -> stage 0
    ra0 = av ? *(const uint4*)(apf) : zu4;
    if (MI == 2) ra1 = av ? *(const uint4*)(apf + 8) : zu4;
    #pragma unroll
    for (int q = 0; q < 2; q++) {
        rb[2*q+0] = *(const float4*)(bpf + 32*q + 0);
        rb[2*q+1] = *(const float4*)(bpf + 32*q + 4);
    }
    {
        *(uint4*)(smem + swA0) = ra0;
        if (MI == 2) *(uint4*)(smem + swA0 + 16) = ra1;
        *(uint4*)(smem + swB0) = cvt8(rb[0], rb[1]);
        *(uint4*)(smem + swB1) = cvt8(rb[2], rb[3]);
    }

    for (int kt = 0; kt < KT; kt++) {
        bool more = (kt + 1 < KT);
        // loads hoisted above the barrier: in flight while warp waits
        if (more) {
            const __half* ap = apf + (kt + 1) * KC;
            const float*  bp = bpf + (kt + 1) * KC;
            ra0 = av ? *(const uint4*)(ap) : zu4;
            if (MI == 2) ra1 = av ? *(const uint4*)(ap + 8) : zu4;
            #pragma unroll
            for (int q = 0; q < 2; q++) {
                rb[2*q+0] = *(const float4*)(bp + 32*q + 0);
                rb[2*q+1] = *(const float4*)(bp + 32*q + 4);
            }
        }
        __syncthreads();

        // MMAs on current stage
        uint32_t st = (uint32_t)(kt & 1) * STAGE;
        uint32_t ab = aBase + st, bb = bBase + st;
        #pragma unroll
        for (int kk = 0; kk < 4; kk++) {
            uint32_t ah[MI][4], bh[2][4];
            #pragma unroll
            for (int mi = 0; mi < MI; mi++)
                LDSM4(ah[mi], ab + mi * (16 * ROWB) + kk * 32);
            #pragma unroll
            for (int j = 0; j < 2; j++)
                LDSM4(bh[j], bb + j * (16 * ROWB) + kk * 32);
            #pragma unroll
            for (int mi = 0; mi < MI; mi++) {
                #pragma unroll
                for (int ns = 0; ns < 4; ns++) {
                    int j = ns >> 1, sel = ns & 1;
                    MMA_F16(c[mi][ns], ah[mi], bh[j][sel], bh[j][sel + 2]);
                }
            }
        }

        // store chunk kt+1 into the other stage
        if (more) {
            char* sb = smem + ((kt + 1) & 1) * STAGE;
            *(uint4*)(sb + swA0) = ra0;
            if (MI == 2) *(uint4*)(sb + swA0 + 16) = ra1;
            *(uint4*)(sb + swB0) = cvt8(rb[0], rb[1]);
            *(uint4*)(sb + swB1) = cvt8(rb[2], rb[3]);
        }
    }

    // ---- epilogue ----
    #pragma unroll
    for (int mi = 0; mi < MI; mi++) {
        int lr0 = m0 + wm * (MI * 16) + mi * 16 + (lane >> 2);
        #pragma unroll
        for (int half_ = 0; half_ < 2; half_++) {
            int lr = lr0 + half_ * 8;
            bool valid = !ROUTED || (lr < cnt);
            if (!valid) continue;
            int orow = ROUTED ? (off + lr) : lr;
            float s = 1.f;
            if (SCALEMODE == 1) s = g_slot_w[off + lr];
            if (SCALEMODE == 2) s = rscale[lr];
            float* cp = C + (size_t)orow * Ntot + n0 + wn * 32 + (lane & 3) * 2;
            #pragma unroll
            for (int ns = 0; ns < 4; ns++) {
                float2 v = make_float2(c[mi][ns][half_ * 2 + 0] * s,
                                       c[mi][ns][half_ * 2 + 1] * s);
                *(float2*)(cp + ns * 8) = v;
            }
        }
    }
}

// ===== R7 dense engine (measured 277us on dense1): 128x256, KC=32 ==========
#define DROWB   80
#define D_AB    (128 * DROWB)
#define D_STG   (D_AB + 256 * DROWB)
#define D_SMEM  (2 * D_STG)

template<int SCALEMODE>
__global__ void __launch_bounds__(512, 1) dense_gemm(
    const __half* __restrict__ A, int lda,
    const float* __restrict__ B,
    float* __restrict__ C, int Ntot, int K,
    const float* __restrict__ rscale)
{
    extern __shared__ char smem[];
    int m0 = blockIdx.y * 128;
    int n0 = blockIdx.x * 256;
    int tid = threadIdx.x;

    int rA = tid >> 2;
    int pA = (tid & 3) << 4;
    const char* aSrc = (const char*)(A + (size_t)(m0 + rA) * lda) + pA;
    uint32_t aDst = (uint32_t)(rA * DROWB + pA);

    int rB = tid >> 1, hB = tid & 1;
    const float* bpf = B + (size_t)(n0 + rB) * K + hB * 16;
    uint32_t bDst = (uint32_t)(D_AB + rB * DROWB + hB * 32);

    uint32_t sm0 = smem_u32(smem);
    int lane = tid & 31, wid = tid >> 5;
    int wm = wid & 3, wn = wid >> 2;
    uint32_t lmoff = (uint32_t)((lane & 15) * DROWB + (lane >> 4) * 16);
    uint32_t aBase = sm0 + (uint32_t)(wm * 32 * DROWB) + lmoff;
    uint32_t bBase = sm0 + D_AB + (uint32_t)(wn * 64 * DROWB) + lmoff;

    float c[2][8][4];
    #pragma unroll
    for (int i = 0; i < 2; i++)
        #pragma unroll
        for (int j = 0; j < 8; j++)
            #pragma unroll
            for (int q = 0; q < 4; q++) c[i][j][q] = 0.f;

    int KT = K / 32;
    float4 rb[4];

    CP_ASYNC16(sm0 + aDst, aSrc, 16);
    CP_COMMIT();
    #pragma unroll
    for (int q = 0; q < 4; q++) rb[q] = *(const float4*)(bpf + 4 * q);
    *(uint4*)(smem + bDst + 0)  = cvt8(rb[0], rb[1]);
    *(uint4*)(smem + bDst + 16) = cvt8(rb[2], rb[3]);

    for (int kt = 0; kt < KT; kt++) {
        CP_WAIT0();
        __syncthreads();
        bool more = (kt + 1 < KT);
        uint32_t stN = (uint32_t)((kt + 1) & 1) * D_STG;
        if (more) {
            CP_ASYNC16(sm0 + stN + aDst, aSrc + (size_t)(kt + 1) * 64, 16);
            CP_COMMIT();
            const float* bp = bpf + (kt + 1) * 32;
            #pragma unroll
            for (int q = 0; q < 4; q++) rb[q] = *(const float4*)(bp + 4 * q);
        }

        uint32_t st = (uint32_t)(kt & 1) * D_STG;
        uint32_t ab = aBase + st, bb = bBase + st;
        #pragma unroll
        for (int kk = 0; kk < 2; kk++) {
            uint32_t ah[2][4], bh[4][4];
            #pragma unroll
            for (int mi = 0; mi < 2; mi++)
                LDSM4(ah[mi], ab + mi * (16 * DROWB) + kk * 32);
            #pragma unroll
            for (int j = 0; j < 4; j++)
                LDSM4(bh[j], bb + j * (16 * DROWB) + kk * 32);
            #pragma unroll
            for (int mi = 0; mi < 2; mi++)
                #pragma unroll
                for (int ns = 0; ns < 8; ns++) {
                    int j = ns >> 1, sel = ns & 1;
                    MMA_F16(c[mi][ns], ah[mi], bh[j][sel], bh[j][sel + 2]);
                }
        }

        if (more) {
            *(uint4*)(smem + stN + bDst + 0)  = cvt8(rb[0], rb[1]);
            *(uint4*)(smem + stN + bDst + 16) = cvt8(rb[2], rb[3]);
        }
    }

    #pragma unroll
    for (int mi = 0; mi < 2; mi++) {
        int lr0 = m0 + wm * 32 + mi * 16 + (lane >> 2);
        #pragma unroll
        for (int half_ = 0; half_ < 2; half_++) {
            int lr = lr0 + half_ * 8;
            float s = 1.f;
            if (SCALEMODE == 2) s = rscale[lr];
            float* cp = C + (size_t)lr * Ntot + n0 + wn * 64 + (lane & 3) * 2;
            #pragma unroll
            for (int ns = 0; ns < 8; ns++) {
                float2 v = make_float2(c[mi][ns][half_ * 2 + 0] * s,
                                       c[mi][ns][half_ * 2 + 1] * s);
                *(float2*)(cp + ns * 8) = v;
            }
        }
    }
}

// ================= launch =================
extern "C" void kernel_launch(void* const* d_in, const int* in_sizes, int n_in,
                              void* d_out, int out_size) {
    const float* x      = (const float*)d_in[0];
    const float* gate_w = (const float*)d_in[1];
    const float* sgw    = (const float*)d_in[2];
    const float* w13    = (const float*)d_in[3];
    const float* w2     = (const float*)d_in[4];
    const float* segu   = (const float*)d_in[5];
    const float* sedw   = (const float*)d_in[6];
    float* out = (float*)d_out;

    int M = in_sizes[0] / H;   // 1024

    float *gu_p, *gur_p, *y_p, *sig_p;
    __half *hsh_p, *hr_p, *x16_p;
    cudaGetSymbolAddress((void**)&gu_p,  g_gu);
    cudaGetSymbolAddress((void**)&gur_p, g_gur);
    cudaGetSymbolAddress((void**)&hsh_p, g_hsh);
    cudaGetSymbolAddress((void**)&hr_p,  g_hr);
    cudaGetSymbolAddress((void**)&y_p,   g_y);
    cudaGetSymbolAddress((void**)&sig_p, g_sig);
    cudaGetSymbolAddress((void**)&x16_p, g_x16);

    const int SMEM_M128 = 2 * (256 * ROWB);   // 73728

    cudaFuncSetAttribute(dense_gemm<0>,     cudaFuncAttributeMaxDynamicSharedMemorySize, D_SMEM);
    cudaFuncSetAttribute(mma_gemm<2,0,0,2>, cudaFuncAttributeMaxDynamicSharedMemorySize, SMEM_M128);
    cudaFuncSetAttribute(mma_gemm<2,1,1,0>, cudaFuncAttributeMaxDynamicSharedMemorySize, SMEM_M128);
    cudaFuncSetAttribute(mma_gemm<2,0,1,1>, cudaFuncAttributeMaxDynamicSharedMemorySize, SMEM_M128);

    // routing pipeline
    zero_counts_kernel<<<1, 64>>>();
    router_kernel<<<M, 256>>>(x, gate_w, sgw);
    scan_kernel<<<1, 32>>>();
    fill_kernel<<<(M + 255) / 256, 256>>>(M);
    x16_kernel<<<(M * H + 255) / 256, 256>>>(x, M * H);

    // shared expert: gate_up on measured-best R7 dense engine
    dense_gemm<0><<<dim3(ISH2 / 256, M / 128), 512, D_SMEM>>>(
        x16_p, H, segu, gu_p, ISH2, H, nullptr);
    silu_mul_kernel<<<1024, 256>>>(gu_p, hsh_p, M, ISH, ISH2);
    // shared expert: down proj on champion engine (fp16 A, scaled)
    mma_gemm<2,0,0,2><<<dim3(H / 128, M / 128), 512, SMEM_M128>>>(
        hsh_p, ISH, sedw, 0, out, H, ISH, sig_p);

    // routed experts: 128-row tiles (one live m-tile per expert ->
    // expert weights read ONCE instead of twice; same padded FLOPs)
    int mtiles = M / 128;   // worst case: all tokens on one expert
    mma_gemm<2,1,1,0><<<dim3(I2 / 128, mtiles, E), 512, SMEM_M128>>>(
        x16_p, H, w13, (size_t)I2 * H, gur_p, I2, H, nullptr);
    silu_mul_kernel<<<1024, 256>>>(gur_p, hr_p, M * TOPK, II, I2);
    mma_gemm<2,0,1,1><<<dim3(H / 128, mtiles, E), 512, SMEM_M128>>>(
        hr_p, II, w2, (size_t)H * II, y_p, H, II, nullptr);

    // deterministic per-token combine
    combine_kernel<<<M, 256>>>(out);
}